// round 6
// baseline (speedup 1.0000x reference)
#include <cuda_runtime.h>
#include <math.h>

// Problem constants
#define Lx  6
#define Hd  512
#define NHd 8
#define FFd 2048
#define Vocab 10000
#define Bd  4
#define Sd  2048
#define DKd 64
#define Nt  (Bd*Sd)     // 8192 tokens
#define QKVW 1536       // fused QKV width

// ---------------- scratch (static device globals; no runtime alloc) ----------------
__device__ float    g_x[Nt*Hd];           // fp32 running activations
__device__ unsigned g_h[Nt*Hd];           // tf32 LN output
__device__ unsigned g_qkv[Nt*QKVW];       // tf32 fused q|k|v
__device__ unsigned g_ctx[Nt*Hd];         // tf32 attention output
__device__ unsigned g_ff[Nt*FFd];         // tf32 FFN hidden
// prepacked tf32 weights
__device__ unsigned g_wqkv[Lx*Hd*QKVW];
__device__ unsigned g_wo[Lx*Hd*Hd];
__device__ unsigned g_w1[Lx*Hd*FFd];
__device__ unsigned g_w2[Lx*FFd*Hd];
__device__ unsigned g_wg[Hd*Vocab];
__device__ float    g_bqkv[Lx*QKVW];

// ---------------- PTX helpers ----------------
__device__ __forceinline__ unsigned f2tf(float x) {
    unsigned r;
    asm("cvt.rna.tf32.f32 %0, %1;" : "=r"(r) : "f"(x));
    return r;
}

__device__ __forceinline__ void mma8(float* c,
                                     unsigned a0, unsigned a1, unsigned a2, unsigned a3,
                                     unsigned b0, unsigned b1) {
    asm volatile(
        "mma.sync.aligned.m16n8k8.row.col.f32.tf32.tf32.f32 "
        "{%0,%1,%2,%3}, {%4,%5,%6,%7}, {%8,%9}, {%0,%1,%2,%3};"
        : "+f"(c[0]), "+f"(c[1]), "+f"(c[2]), "+f"(c[3])
        : "r"(a0), "r"(a1), "r"(a2), "r"(a3), "r"(b0), "r"(b1));
}

__device__ __forceinline__ void cpa16(unsigned dst, const void* src) {
    asm volatile("cp.async.ca.shared.global [%0], [%1], 16;" :: "r"(dst), "l"(src));
}
__device__ __forceinline__ void cpa16p(unsigned dst, const void* src, int bytes) {
    asm volatile("cp.async.ca.shared.global [%0], [%1], 16, %2;" :: "r"(dst), "l"(src), "r"(bytes));
}
__device__ __forceinline__ void cp_commit() { asm volatile("cp.async.commit_group;"); }
template<int N> __device__ __forceinline__ void cp_wait() {
    asm volatile("cp.async.wait_group %0;" :: "n"(N));
}

// ---------------- weight prepack ----------------
__global__ void pack_qkv_kernel(const float* __restrict__ Wq,
                                const float* __restrict__ Wk,
                                const float* __restrict__ Wv,
                                unsigned* __restrict__ dst)
{
    for (int idx = blockIdx.x * blockDim.x + threadIdx.x;
         idx < Lx*Hd*QKVW; idx += gridDim.x * blockDim.x) {
        int l = idx / (Hd*QKVW);
        int rem = idx - l * Hd*QKVW;
        int k = rem / QKVW;
        int n = rem - k * QKVW;
        float val;
        if (n < Hd)            val = Wq[(size_t)l*Hd*Hd + k*Hd + n];
        else if (n < 2*Hd)     val = Wk[(size_t)l*Hd*Hd + k*Hd + (n - Hd)];
        else                   val = Wv[(size_t)l*Hd*Hd + k*Hd + (n - 2*Hd)];
        dst[idx] = f2tf(val);
    }
}

__global__ void pack_bqkv_kernel(const float* __restrict__ bq,
                                 const float* __restrict__ bk,
                                 const float* __restrict__ bv,
                                 float* __restrict__ dst)
{
    int idx = blockIdx.x * blockDim.x + threadIdx.x;
    if (idx >= Lx*QKVW) return;
    int l = idx / QKVW;
    int n = idx - l * QKVW;
    float val;
    if (n < Hd)        val = bq[l*Hd + n];
    else if (n < 2*Hd) val = bk[l*Hd + (n - Hd)];
    else               val = bv[l*Hd + (n - 2*Hd)];
    dst[idx] = val;
}

__global__ void convert_kernel(const float* __restrict__ src,
                               unsigned* __restrict__ dst, int count)
{
    for (int i = blockIdx.x * blockDim.x + threadIdx.x;
         i < count; i += gridDim.x * blockDim.x)
        dst[i] = f2tf(src[i]);
}

// ---------------- embedding + sinusoidal positional encoding ----------------
__global__ void embed_kernel(const int* __restrict__ src,
                             const float* __restrict__ emb,
                             float* __restrict__ x)
{
    int idx = blockIdx.x * blockDim.x + threadIdx.x;
    if (idx >= Nt*Hd) return;
    int n = idx >> 9;
    int c = idx & (Hd-1);
    int s = n & (Sd-1);
    int tok = src[n];
    int i2 = c & ~1;
    float div = expf(-(logf(10000.0f)/(float)Hd) * (float)i2);
    float ang = (float)s * div;
    float pe = (c & 1) ? cosf(ang) : sinf(ang);
    x[idx] = emb[(size_t)tok*Hd + c] + pe;
}

// ---------------- layernorm: fp32 in -> tf32 bits out ----------------
__global__ void layernorm_kernel(const float* __restrict__ x,
                                 const float* __restrict__ g,
                                 const float* __restrict__ b,
                                 unsigned* __restrict__ out)
{
    int row = blockIdx.x;
    int tid = threadIdx.x;
    const float* xr = x + (size_t)row*Hd;
    float4 v = *reinterpret_cast<const float4*>(xr + tid*4);

    __shared__ float red[4];
    __shared__ float red2[4];

    float s = v.x + v.y + v.z + v.w;
    #pragma unroll
    for (int o = 16; o > 0; o >>= 1) s += __shfl_xor_sync(0xffffffffu, s, o);
    if ((tid & 31) == 0) red[tid >> 5] = s;
    __syncthreads();
    float mean = (red[0] + red[1] + red[2] + red[3]) * (1.0f/(float)Hd);

    float dx = v.x - mean, dy = v.y - mean, dz = v.z - mean, dw = v.w - mean;
    float ss = dx*dx + dy*dy + dz*dz + dw*dw;
    #pragma unroll
    for (int o = 16; o > 0; o >>= 1) ss += __shfl_xor_sync(0xffffffffu, ss, o);
    if ((tid & 31) == 0) red2[tid >> 5] = ss;
    __syncthreads();
    float var = (red2[0] + red2[1] + red2[2] + red2[3]) * (1.0f/(float)Hd);
    float rstd = rsqrtf(var + 1e-5f);

    int c = tid*4;
    float4 gg = *reinterpret_cast<const float4*>(g + c);
    float4 bb = *reinterpret_cast<const float4*>(b + c);
    uint4 o4;
    o4.x = f2tf(dx*rstd*gg.x + bb.x);
    o4.y = f2tf(dy*rstd*gg.y + bb.y);
    o4.z = f2tf(dz*rstd*gg.z + bb.z);
    o4.w = f2tf(dw*rstd*gg.w + bb.w);
    *reinterpret_cast<uint4*>(out + (size_t)row*Hd + c) = o4;
}

// ============================================================================
// Prepacked GEMM: A, B are tf32 bits (u32). No cvt in inner loop.
// OUT modes: 0 = f32 + residual, 1 = tf32, 2 = tf32+relu,
//            3 = tf32 with cols<Hd scaled by 0.125 (fused QKV), 4 = f32 plain
// ============================================================================
template<int OM>
__global__ void __launch_bounds__(256, 2)
gemm_pk(const unsigned* __restrict__ A,
        const unsigned* __restrict__ B,
        const float* __restrict__ bias,
        const float* __restrict__ R,
        void* __restrict__ Cv,
        int M, int N, int K)
{
    __shared__ __align__(16) unsigned As[2][128][20];
    __shared__ __align__(16) unsigned Bs[2][16][132];

    int tid = threadIdx.x;
    int wid = tid >> 5, lane = tid & 31;
    int g = lane >> 2, t = lane & 3;
    int wm = (wid >> 2) * 64;
    int wn = (wid & 3) * 32;
    int rowBase = blockIdx.y * 128;
    int colBase = blockIdx.x * 128;

    float acc[4][4][4];
    #pragma unroll
    for (int mi = 0; mi < 4; mi++)
        #pragma unroll
        for (int ni = 0; ni < 4; ni++)
            #pragma unroll
            for (int r = 0; r < 4; r++) acc[mi][ni][r] = 0.0f;

    int nstages = K >> 4;

    auto loadStage = [&](int st, int k0) {
        #pragma unroll
        for (int i = 0; i < 2; i++) {
            int li = tid + i * 256;
            int r = li >> 2, kq = (li & 3) * 4;
            unsigned d = (unsigned)__cvta_generic_to_shared(&As[st][r][kq]);
            cpa16(d, &A[(size_t)(rowBase + r) * K + k0 + kq]);
        }
        #pragma unroll
        for (int i = 0; i < 2; i++) {
            int li = tid + i * 256;
            int r = li >> 5, cq = (li & 31) * 4;
            unsigned d = (unsigned)__cvta_generic_to_shared(&Bs[st][r][cq]);
            int gc = colBase + cq;
            cpa16p(d, &B[(size_t)(k0 + r) * N + gc], (gc + 4 <= N) ? 16 : 0);
        }
        cp_commit();
    };

    auto computeStage = [&](int st) {
        #pragma unroll
        for (int kk = 0; kk < 16; kk += 8) {
            unsigned a[4][4], b[4][2];
            #pragma unroll
            for (int mi = 0; mi < 4; mi++) {
                int m = wm + mi * 16 + g;
                a[mi][0] = As[st][m    ][kk + t];
                a[mi][1] = As[st][m + 8][kk + t];
                a[mi][2] = As[st][m    ][kk + 4 + t];
                a[mi][3] = As[st][m + 8][kk + 4 + t];
            }
            #pragma unroll
            for (int ni = 0; ni < 4; ni++) {
                int n = wn + ni * 8 + g;
                b[ni][0] = Bs[st][kk + t    ][n];
                b[ni][1] = Bs[st][kk + 4 + t][n];
            }
            #pragma unroll
            for (int mi = 0; mi < 4; mi++)
                #pragma unroll
                for (int ni = 0; ni < 4; ni++)
                    mma8(acc[mi][ni], a[mi][0], a[mi][1], a[mi][2], a[mi][3],
                         b[ni][0], b[ni][1]);
        }
    };

    loadStage(0, 0);
    for (int s = 0; s < nstages; s++) {
        if (s + 1 < nstages) {
            loadStage((s + 1) & 1, (s + 1) * 16);
            cp_wait<1>();
        } else {
            cp_wait<0>();
        }
        __syncthreads();
        computeStage(s & 1);
        __syncthreads();
    }

    #pragma unroll
    for (int mi = 0; mi < 4; mi++) {
        #pragma unroll
        for (int ni = 0; ni < 4; ni++) {
            int r0 = rowBase + wm + mi * 16 + g;
            int c0 = colBase + wn + ni * 8 + 2 * t;
            if (c0 < N) {
                float bx = bias[c0], by = bias[c0 + 1];
                float v00 = acc[mi][ni][0] + bx;
                float v01 = acc[mi][ni][1] + by;
                float v10 = acc[mi][ni][2] + bx;
                float v11 = acc[mi][ni][3] + by;
                if (OM == 0) {
                    float* C = (float*)Cv;
                    float2 ra = *(const float2*)&R[(size_t)r0 * N + c0];
                    float2 rb = *(const float2*)&R[(size_t)(r0 + 8) * N + c0];
                    *(float2*)&C[(size_t)r0 * N + c0]       = make_float2(v00 + ra.x, v01 + ra.y);
                    *(float2*)&C[(size_t)(r0 + 8) * N + c0] = make_float2(v10 + rb.x, v11 + rb.y);
                } else if (OM == 4) {
                    float* C = (float*)Cv;
                    *(float2*)&C[(size_t)r0 * N + c0]       = make_float2(v00, v01);
                    *(float2*)&C[(size_t)(r0 + 8) * N + c0] = make_float2(v10, v11);
                } else {
                    if (OM == 2) {
                        v00 = fmaxf(v00, 0.f); v01 = fmaxf(v01, 0.f);
                        v10 = fmaxf(v10, 0.f); v11 = fmaxf(v11, 0.f);
                    }
                    if (OM == 3 && c0 < Hd) {
                        v00 *= 0.125f; v01 *= 0.125f;
                        v10 *= 0.125f; v11 *= 0.125f;
                    }
                    unsigned* C = (unsigned*)Cv;
                    uint2 u0 = make_uint2(f2tf(v00), f2tf(v01));
                    uint2 u1 = make_uint2(f2tf(v10), f2tf(v11));
                    *(uint2*)&C[(size_t)r0 * N + c0]       = u0;
                    *(uint2*)&C[(size_t)(r0 + 8) * N + c0] = u1;
                }
            }
        }
    }
}

// ============================================================================
// Flash attention on tf32-bit inputs (q pre-scaled). Output: tf32 bits.
// ============================================================================
#define KSP 68
#define VSP 72
#define PSP 132
#define FLASH_SMEM ((2*128*KSP + 2*128*VSP + 128*PSP) * 4 + 256)

__global__ void __launch_bounds__(256, 1)
flash_attn(const unsigned* __restrict__ qkv,
           const unsigned char* __restrict__ mask,
           unsigned* __restrict__ ctx)
{
    extern __shared__ char smem_raw[];
    unsigned* Ks = (unsigned*)smem_raw;                   // 2*128*KSP
    unsigned* Vs = Ks + 2*128*KSP;                        // 2*128*VSP
    unsigned* Ps = Vs + 2*128*VSP;                        // 128*PSP
    unsigned char* Ms = (unsigned char*)(Ps + 128*PSP);   // 2*128

    int bi = blockIdx.y;
    int b = bi >> 3, h = bi & 7;
    int qBase = blockIdx.x * 128;
    const unsigned* Qg = qkv + (size_t)b*Sd*QKVW + h*DKd;
    const unsigned* Kg = qkv + (size_t)b*Sd*QKVW + Hd   + h*DKd;
    const unsigned* Vg = qkv + (size_t)b*Sd*QKVW + 2*Hd + h*DKd;
    const unsigned char* mr = mask + (size_t)b*Sd;
    unsigned* Cg = ctx + (size_t)b*Sd*Hd + h*DKd;

    int tid = threadIdx.x;
    int wid = tid >> 5, lane = tid & 31;
    int g = lane >> 2, t = lane & 3;
    int wm = wid * 16;

    // Q fragments: already tf32 bits, already scaled by 1/8
    unsigned qf[8][4];
    {
        int r0 = qBase + wm + g, r1 = r0 + 8;
        #pragma unroll
        for (int kk = 0; kk < 8; kk++) {
            qf[kk][0] = Qg[(size_t)r0*QKVW + kk*8 + t];
            qf[kk][1] = Qg[(size_t)r1*QKVW + kk*8 + t];
            qf[kk][2] = Qg[(size_t)r0*QKVW + kk*8 + 4 + t];
            qf[kk][3] = Qg[(size_t)r1*QKVW + kk*8 + 4 + t];
        }
    }

    float m0 = -1e30f, m1 = -1e30f, l0 = 0.f, l1 = 0.f;
    float o[8][4];
    #pragma unroll
    for (int i = 0; i < 8; i++)
        #pragma unroll
        for (int r = 0; r < 4; r++) o[i][r] = 0.f;

    auto loadTile = [&](int kt, int buf) {
        unsigned* Ktile = Ks + buf*128*KSP;
        unsigned* Vtile = Vs + buf*128*VSP;
        #pragma unroll
        for (int i = 0; i < 8; i++) {
            int li = tid + i * 256;
            int r = li >> 4, cq = (li & 15) * 4;
            cpa16((unsigned)__cvta_generic_to_shared(&Ktile[r*KSP + cq]),
                  &Kg[(size_t)(kt*128 + r)*QKVW + cq]);
            cpa16((unsigned)__cvta_generic_to_shared(&Vtile[r*VSP + cq]),
                  &Vg[(size_t)(kt*128 + r)*QKVW + cq]);
        }
        if (tid < 32) {
            uchar4 mv = *(const uchar4*)&mr[kt*128 + tid*4];
            *(uchar4*)&Ms[buf*128 + tid*4] = mv;
        }
        cp_commit();
    };

    const int NT = Sd / 128;   // 16
    loadTile(0, 0);

    for (int kt = 0; kt < NT; kt++) {
        int buf = kt & 1;
        if (kt + 1 < NT) { loadTile(kt + 1, buf ^ 1); cp_wait<1>(); }
        else             { cp_wait<0>(); }
        __syncthreads();

        const unsigned* Ktile = Ks + buf*128*KSP;
        const unsigned* Vtile = Vs + buf*128*VSP;
        const unsigned char* Mt = Ms + buf*128;

        // ---- S = Q K^T ----
        float s[16][4];
        #pragma unroll
        for (int ni = 0; ni < 16; ni++)
            #pragma unroll
            for (int r = 0; r < 4; r++) s[ni][r] = 0.f;

        #pragma unroll
        for (int kk = 0; kk < 8; kk++) {
            #pragma unroll
            for (int ni = 0; ni < 16; ni++) {
                int n = ni*8 + g;
                unsigned b0 = Ktile[n*KSP + kk*8 + t];
                unsigned b1 = Ktile[n*KSP + kk*8 + 4 + t];
                mma8(s[ni], qf[kk][0], qf[kk][1], qf[kk][2], qf[kk][3], b0, b1);
            }
        }

        // ---- mask + row max ----
        float mt0 = -1e30f, mt1 = -1e30f;
        #pragma unroll
        for (int ni = 0; ni < 16; ni++) {
            int c = ni*8 + 2*t;
            if (Mt[c])     { s[ni][0] = -1e30f; s[ni][2] = -1e30f; }
            if (Mt[c + 1]) { s[ni][1] = -1e30f; s[ni][3] = -1e30f; }
            mt0 = fmaxf(mt0, fmaxf(s[ni][0], s[ni][1]));
            mt1 = fmaxf(mt1, fmaxf(s[ni][2], s[ni][3]));
        }
        mt0 = fmaxf(mt0, __shfl_xor_sync(0xffffffffu, mt0, 1));
        mt0 = fmaxf(mt0, __shfl_xor_sync(0xffffffffu, mt0, 2));
        mt1 = fmaxf(mt1, __shfl_xor_sync(0xffffffffu, mt1, 1));
        mt1 = fmaxf(mt1, __shfl_xor_sync(0xffffffffu, mt1, 2));

        float mn0 = fmaxf(m0, mt0), mn1 = fmaxf(m1, mt1);
        float c0 = __expf(m0 - mn0), c1 = __expf(m1 - mn1);
        m0 = mn0; m1 = mn1;

        // ---- exp, row sums, write P (tf32) ----
        float rs0 = 0.f, rs1 = 0.f;
        #pragma unroll
        for (int ni = 0; ni < 16; ni++) {
            float p0 = __expf(s[ni][0] - m0);
            float p1 = __expf(s[ni][1] - m0);
            float p2 = __expf(s[ni][2] - m1);
            float p3 = __expf(s[ni][3] - m1);
            rs0 += p0 + p1;
            rs1 += p2 + p3;
            int row = wm + g;
            int col = ni*8 + 2*t;
            Ps[row*PSP + col]       = f2tf(p0);
            Ps[row*PSP + col + 1]   = f2tf(p1);
            Ps[(row+8)*PSP + col]   = f2tf(p2);
            Ps[(row+8)*PSP + col+1] = f2tf(p3);
        }
        rs0 += __shfl_xor_sync(0xffffffffu, rs0, 1);
        rs0 += __shfl_xor_sync(0xffffffffu, rs0, 2);
        rs1 += __shfl_xor_sync(0xffffffffu, rs1, 1);
        rs1 += __shfl_xor_sync(0xffffffffu, rs1, 2);
        l0 = l0 * c0 + rs0;
        l1 = l1 * c1 + rs1;

        #pragma unroll
        for (int oni = 0; oni < 8; oni++) {
            o[oni][0] *= c0; o[oni][1] *= c0;
            o[oni][2] *= c1; o[oni][3] *= c1;
        }

        __syncwarp();

        // ---- O += P V ----
        #pragma unroll
        for (int kk = 0; kk < 16; kk++) {
            unsigned a0 = Ps[(wm + g)*PSP     + kk*8 + t];
            unsigned a1 = Ps[(wm + 8 + g)*PSP + kk*8 + t];
            unsigned a2 = Ps[(wm + g)*PSP     + kk*8 + 4 + t];
            unsigned a3 = Ps[(wm + 8 + g)*PSP + kk*8 + 4 + t];
            #pragma unroll
            for (int oni = 0; oni < 8; oni++) {
                unsigned b0 = Vtile[(kk*8 + t)*VSP     + oni*8 + g];
                unsigned b1 = Vtile[(kk*8 + 4 + t)*VSP + oni*8 + g];
                mma8(o[oni], a0, a1, a2, a3, b0, b1);
            }
        }
        __syncthreads();
    }

    // ---- epilogue: divide by l, write ctx as tf32 bits ----
    float i0 = 1.f / l0, i1 = 1.f / l1;
    int r0 = qBase + wm + g, r1 = r0 + 8;
    #pragma unroll
    for (int oni = 0; oni < 8; oni++) {
        int c = oni*8 + 2*t;
        uint2 u0 = make_uint2(f2tf(o[oni][0] * i0), f2tf(o[oni][1] * i0));
        uint2 u1 = make_uint2(f2tf(o[oni][2] * i1), f2tf(o[oni][3] * i1));
        *(uint2*)&Cg[(size_t)r0*Hd + c] = u0;
        *(uint2*)&Cg[(size_t)r1*Hd + c] = u1;
    }
}

// ---------------- launch ----------------
extern "C" void kernel_launch(void* const* d_in, const int* in_sizes, int n_in,
                              void* d_out, int out_size)
{
    const int*           src  = (const int*)d_in[0];
    const unsigned char* mask = (const unsigned char*)d_in[1];
    const float* emb  = (const float*)d_in[2];
    const float* Wq   = (const float*)d_in[3];
    const float* bq   = (const float*)d_in[4];
    const float* Wk   = (const float*)d_in[5];
    const float* bk   = (const float*)d_in[6];
    const float* Wv   = (const float*)d_in[7];
    const float* bv   = (const float*)d_in[8];
    const float* Wo   = (const float*)d_in[9];
    const float* bo   = (const float*)d_in[10];
    const float* ln1g = (const float*)d_in[11];
    const float* ln1b = (const float*)d_in[12];
    const float* W1   = (const float*)d_in[13];
    const float* b1   = (const float*)d_in[14];
    const float* W2   = (const float*)d_in[15];
    const float* b2   = (const float*)d_in[16];
    const float* ln2g = (const float*)d_in[17];
    const float* ln2b = (const float*)d_in[18];
    const float* lnfg = (const float*)d_in[19];
    const float* lnfb = (const float*)d_in[20];
    const float* Wg   = (const float*)d_in[21];
    const float* bg   = (const float*)d_in[22];
    float* out = (float*)d_out;

    float *x;   unsigned *h, *qkv, *ctx, *ff;
    unsigned *wqkv, *wo, *w1, *w2, *wg;  float *bqkv;
    cudaGetSymbolAddress((void**)&x,    g_x);
    cudaGetSymbolAddress((void**)&h,    g_h);
    cudaGetSymbolAddress((void**)&qkv,  g_qkv);
    cudaGetSymbolAddress((void**)&ctx,  g_ctx);
    cudaGetSymbolAddress((void**)&ff,   g_ff);
    cudaGetSymbolAddress((void**)&wqkv, g_wqkv);
    cudaGetSymbolAddress((void**)&wo,   g_wo);
    cudaGetSymbolAddress((void**)&w1,   g_w1);
    cudaGetSymbolAddress((void**)&w2,   g_w2);
    cudaGetSymbolAddress((void**)&wg,   g_wg);
    cudaGetSymbolAddress((void**)&bqkv, g_bqkv);

    static bool attr_set = false;
    if (!attr_set) {
        cudaFuncSetAttribute(flash_attn,
                             cudaFuncAttributeMaxDynamicSharedMemorySize, FLASH_SMEM);
        attr_set = true;
    }

    // ---- prepack weights to tf32 bits ----
    pack_qkv_kernel<<<1184, 256>>>(Wq, Wk, Wv, wqkv);
    pack_bqkv_kernel<<<(Lx*QKVW + 255)/256, 256>>>(bq, bk, bv, bqkv);
    convert_kernel<<<1184, 256>>>(Wo, wo, Lx*Hd*Hd);
    convert_kernel<<<1184, 256>>>(W1, w1, Lx*Hd*FFd);
    convert_kernel<<<1184, 256>>>(W2, w2, Lx*FFd*Hd);
    convert_kernel<<<1184, 256>>>(Wg, wg, Hd*Vocab);

    embed_kernel<<<(Nt*Hd + 255)/256, 256>>>(src, emb, x);

    dim3 gQKV(QKVW/128, Nt/128);       // N=1536
    dim3 gH(Hd/128,  Nt/128);          // N=512
    dim3 gF(FFd/128, Nt/128);          // N=2048
    dim3 gV((Vocab+127)/128, Nt/128);  // N=10000

    for (int l = 0; l < Lx; l++) {
        layernorm_kernel<<<Nt, 128>>>(x, ln1g + (size_t)l*Hd, ln1b + (size_t)l*Hd, h);

        // fused QKV: qkv = h @ Wqkv + bqkv (q cols scaled by 1/8, tf32 out)
        gemm_pk<3><<<gQKV, 256>>>(h, wqkv + (size_t)l*Hd*QKVW, bqkv + (size_t)l*QKVW,
                                  nullptr, qkv, Nt, QKVW, Hd);

        flash_attn<<<dim3(Sd/128, Bd*NHd), 256, FLASH_SMEM>>>(qkv, mask, ctx);

        // x = x + ctx @ Wo + bo
        gemm_pk<0><<<gH, 256>>>(ctx, wo + (size_t)l*Hd*Hd, bo + (size_t)l*Hd,
                                x, x, Nt, Hd, Hd);

        layernorm_kernel<<<Nt, 128>>>(x, ln2g + (size_t)l*Hd, ln2b + (size_t)l*Hd, h);

        // ff = relu(h @ W1 + b1) (tf32 out)
        gemm_pk<2><<<gF, 256>>>(h, w1 + (size_t)l*Hd*FFd, b1 + (size_t)l*FFd,
                                nullptr, ff, Nt, FFd, Hd);
        // x = x + ff @ W2 + b2
        gemm_pk<0><<<gH, 256>>>(ff, w2 + (size_t)l*FFd*Hd, b2 + (size_t)l*Hd,
                                x, x, Nt, Hd, FFd);
    }

    layernorm_kernel<<<Nt, 128>>>(x, lnfg, lnfb, h);
    gemm_pk<4><<<gV, 256>>>(h, wg, bg, nullptr, out, Nt, Vocab, Hd);
}

// round 8
// speedup vs baseline: 1.0621x; 1.0621x over previous
#include <cuda_runtime.h>
#include <math.h>

// Problem constants
#define Lx  6
#define Hd  512
#define NHd 8
#define FFd 2048
#define Vocab 10000
#define Bd  4
#define Sd  2048
#define DKd 64
#define Nt  (Bd*Sd)     // 8192 tokens
#define QKVW 1536       // fused QKV width

// ---------------- scratch (static device globals; no runtime alloc) ----------------
__device__ float    g_x[Nt*Hd];           // fp32 running activations
__device__ unsigned g_h[Nt*Hd];           // tf32 LN output
__device__ unsigned g_qkv[Nt*QKVW];       // tf32 fused q|k|v
__device__ unsigned g_ctx[Nt*Hd];         // tf32 attention output
__device__ unsigned g_ff[Nt*FFd];         // tf32 FFN hidden
// prepacked tf32 weights
__device__ unsigned g_wqkv[Lx*Hd*QKVW];
__device__ unsigned g_wo[Lx*Hd*Hd];
__device__ unsigned g_w1[Lx*Hd*FFd];
__device__ unsigned g_w2[Lx*FFd*Hd];
__device__ unsigned g_wg[Hd*Vocab];
__device__ float    g_bqkv[Lx*QKVW];

// ---------------- PTX helpers ----------------
__device__ __forceinline__ unsigned f2tf(float x) {
    unsigned r;
    asm("cvt.rna.tf32.f32 %0, %1;" : "=r"(r) : "f"(x));
    return r;
}

__device__ __forceinline__ void mma8(float* c,
                                     unsigned a0, unsigned a1, unsigned a2, unsigned a3,
                                     unsigned b0, unsigned b1) {
    asm volatile(
        "mma.sync.aligned.m16n8k8.row.col.f32.tf32.tf32.f32 "
        "{%0,%1,%2,%3}, {%4,%5,%6,%7}, {%8,%9}, {%0,%1,%2,%3};"
        : "+f"(c[0]), "+f"(c[1]), "+f"(c[2]), "+f"(c[3])
        : "r"(a0), "r"(a1), "r"(a2), "r"(a3), "r"(b0), "r"(b1));
}

__device__ __forceinline__ void cpa16(unsigned dst, const void* src) {
    asm volatile("cp.async.ca.shared.global [%0], [%1], 16;" :: "r"(dst), "l"(src));
}
__device__ __forceinline__ void cpa16p(unsigned dst, const void* src, int bytes) {
    asm volatile("cp.async.ca.shared.global [%0], [%1], 16, %2;" :: "r"(dst), "l"(src), "r"(bytes));
}
__device__ __forceinline__ void cp_commit() { asm volatile("cp.async.commit_group;"); }
template<int N> __device__ __forceinline__ void cp_wait() {
    asm volatile("cp.async.wait_group %0;" :: "n"(N));
}

// ---------------- weight prepack ----------------
__global__ void pack_qkv_kernel(const float* __restrict__ Wq,
                                const float* __restrict__ Wk,
                                const float* __restrict__ Wv,
                                unsigned* __restrict__ dst)
{
    for (int idx = blockIdx.x * blockDim.x + threadIdx.x;
         idx < Lx*Hd*QKVW; idx += gridDim.x * blockDim.x) {
        int l = idx / (Hd*QKVW);
        int rem = idx - l * Hd*QKVW;
        int k = rem / QKVW;
        int n = rem - k * QKVW;
        float val;
        if (n < Hd)            val = Wq[(size_t)l*Hd*Hd + k*Hd + n];
        else if (n < 2*Hd)     val = Wk[(size_t)l*Hd*Hd + k*Hd + (n - Hd)];
        else                   val = Wv[(size_t)l*Hd*Hd + k*Hd + (n - 2*Hd)];
        dst[idx] = f2tf(val);
    }
}

__global__ void pack_bqkv_kernel(const float* __restrict__ bq,
                                 const float* __restrict__ bk,
                                 const float* __restrict__ bv,
                                 float* __restrict__ dst)
{
    int idx = blockIdx.x * blockDim.x + threadIdx.x;
    if (idx >= Lx*QKVW) return;
    int l = idx / QKVW;
    int n = idx - l * QKVW;
    float val;
    if (n < Hd)        val = bq[l*Hd + n];
    else if (n < 2*Hd) val = bk[l*Hd + (n - Hd)];
    else               val = bv[l*Hd + (n - 2*Hd)];
    dst[idx] = val;
}

__global__ void convert_kernel(const float* __restrict__ src,
                               unsigned* __restrict__ dst, int count)
{
    for (int i = blockIdx.x * blockDim.x + threadIdx.x;
         i < count; i += gridDim.x * blockDim.x)
        dst[i] = f2tf(src[i]);
}

// ---------------- embedding + sinusoidal positional encoding ----------------
__global__ void embed_kernel(const int* __restrict__ src,
                             const float* __restrict__ emb,
                             float* __restrict__ x)
{
    int idx = blockIdx.x * blockDim.x + threadIdx.x;
    if (idx >= Nt*Hd) return;
    int n = idx >> 9;
    int c = idx & (Hd-1);
    int s = n & (Sd-1);
    int tok = src[n];
    int i2 = c & ~1;
    float div = expf(-(logf(10000.0f)/(float)Hd) * (float)i2);
    float ang = (float)s * div;
    float pe = (c & 1) ? cosf(ang) : sinf(ang);
    x[idx] = emb[(size_t)tok*Hd + c] + pe;
}

// ---------------- layernorm: fp32 in -> tf32 bits out ----------------
__global__ void layernorm_kernel(const float* __restrict__ x,
                                 const float* __restrict__ g,
                                 const float* __restrict__ b,
                                 unsigned* __restrict__ out)
{
    int row = blockIdx.x;
    int tid = threadIdx.x;
    const float* xr = x + (size_t)row*Hd;
    float4 v = *reinterpret_cast<const float4*>(xr + tid*4);

    __shared__ float red[4];
    __shared__ float red2[4];

    float s = v.x + v.y + v.z + v.w;
    #pragma unroll
    for (int o = 16; o > 0; o >>= 1) s += __shfl_xor_sync(0xffffffffu, s, o);
    if ((tid & 31) == 0) red[tid >> 5] = s;
    __syncthreads();
    float mean = (red[0] + red[1] + red[2] + red[3]) * (1.0f/(float)Hd);

    float dx = v.x - mean, dy = v.y - mean, dz = v.z - mean, dw = v.w - mean;
    float ss = dx*dx + dy*dy + dz*dz + dw*dw;
    #pragma unroll
    for (int o = 16; o > 0; o >>= 1) ss += __shfl_xor_sync(0xffffffffu, ss, o);
    if ((tid & 31) == 0) red2[tid >> 5] = ss;
    __syncthreads();
    float var = (red2[0] + red2[1] + red2[2] + red2[3]) * (1.0f/(float)Hd);
    float rstd = rsqrtf(var + 1e-5f);

    int c = tid*4;
    float4 gg = *reinterpret_cast<const float4*>(g + c);
    float4 bb = *reinterpret_cast<const float4*>(b + c);
    uint4 o4;
    o4.x = f2tf(dx*rstd*gg.x + bb.x);
    o4.y = f2tf(dy*rstd*gg.y + bb.y);
    o4.z = f2tf(dz*rstd*gg.z + bb.z);
    o4.w = f2tf(dw*rstd*gg.w + bb.w);
    *reinterpret_cast<uint4*>(out + (size_t)row*Hd + c) = o4;
}

// ============================================================================
// Prepacked GEMM: A, B tf32 bits. 128x128 tile, KT=32, 3-stage cp.async
// pipeline, ONE __syncthreads per k-tile.
// OUT modes: 0 = f32 + residual, 2 = tf32+relu,
//            3 = tf32 with cols<Hd scaled by 0.125 (fused QKV), 4 = f32 plain
// ============================================================================
#define GKT 32
#define ASP 36
#define BSP 132
#define GEMM_SMEM ((3*128*ASP + 3*GKT*BSP) * 4)

template<int OM>
__global__ void __launch_bounds__(256, 2)
gemm_pk(const unsigned* __restrict__ A,
        const unsigned* __restrict__ B,
        const float* __restrict__ bias,
        const float* __restrict__ R,
        void* __restrict__ Cv,
        int M, int N, int K)
{
    extern __shared__ unsigned gsm[];
    unsigned* As = gsm;                 // [3][128][ASP]
    unsigned* Bs = gsm + 3*128*ASP;     // [3][GKT][BSP]

    int tid = threadIdx.x;
    int wid = tid >> 5, lane = tid & 31;
    int g = lane >> 2, t = lane & 3;
    int wm = (wid >> 2) * 64;
    int wn = (wid & 3) * 32;
    int rowBase = blockIdx.y * 128;
    int colBase = blockIdx.x * 128;

    float acc[4][4][4];
    #pragma unroll
    for (int mi = 0; mi < 4; mi++)
        #pragma unroll
        for (int ni = 0; ni < 4; ni++)
            #pragma unroll
            for (int r = 0; r < 4; r++) acc[mi][ni][r] = 0.0f;

    int nst = K / GKT;

    auto loadStage = [&](int st, int k0) {
        unsigned* Adst = As + st*128*ASP;
        unsigned* Bdst = Bs + st*GKT*BSP;
        #pragma unroll
        for (int i = 0; i < 4; i++) {
            int li = tid + i * 256;
            int r = li >> 3, kq = (li & 7) * 4;
            cpa16((unsigned)__cvta_generic_to_shared(&Adst[r*ASP + kq]),
                  &A[(size_t)(rowBase + r) * K + k0 + kq]);
        }
        #pragma unroll
        for (int i = 0; i < 4; i++) {
            int li = tid + i * 256;
            int r = li >> 5, cq = (li & 31) * 4;
            int gc = colBase + cq;
            cpa16p((unsigned)__cvta_generic_to_shared(&Bdst[r*BSP + cq]),
                   &B[(size_t)(k0 + r) * N + gc], (gc + 4 <= N) ? 16 : 0);
        }
        cp_commit();
    };

    auto computeStage = [&](int st) {
        const unsigned* Asrc = As + st*128*ASP;
        const unsigned* Bsrc = Bs + st*GKT*BSP;
        #pragma unroll
        for (int kk = 0; kk < GKT; kk += 8) {
            unsigned a[4][4], b[4][2];
            #pragma unroll
            for (int mi = 0; mi < 4; mi++) {
                int m = wm + mi * 16 + g;
                a[mi][0] = Asrc[m*ASP       + kk + t];
                a[mi][1] = Asrc[(m + 8)*ASP + kk + t];
                a[mi][2] = Asrc[m*ASP       + kk + 4 + t];
                a[mi][3] = Asrc[(m + 8)*ASP + kk + 4 + t];
            }
            #pragma unroll
            for (int ni = 0; ni < 4; ni++) {
                int n = wn + ni * 8 + g;
                b[ni][0] = Bsrc[(kk + t)*BSP     + n];
                b[ni][1] = Bsrc[(kk + 4 + t)*BSP + n];
            }
            #pragma unroll
            for (int mi = 0; mi < 4; mi++)
                #pragma unroll
                for (int ni = 0; ni < 4; ni++)
                    mma8(acc[mi][ni], a[mi][0], a[mi][1], a[mi][2], a[mi][3],
                         b[ni][0], b[ni][1]);
        }
    };

    loadStage(0, 0);
    if (nst > 1) loadStage(1, GKT);

    for (int s = 0; s < nst; s++) {
        cp_wait<1>();
        __syncthreads();
        computeStage(s % 3);
        if (s + 2 < nst) loadStage((s + 2) % 3, (s + 2) * GKT);
    }

    #pragma unroll
    for (int mi = 0; mi < 4; mi++) {
        #pragma unroll
        for (int ni = 0; ni < 4; ni++) {
            int r0 = rowBase + wm + mi * 16 + g;
            int c0 = colBase + wn + ni * 8 + 2 * t;
            if (c0 < N) {
                float bx = bias[c0], by = bias[c0 + 1];
                float v00 = acc[mi][ni][0] + bx;
                float v01 = acc[mi][ni][1] + by;
                float v10 = acc[mi][ni][2] + bx;
                float v11 = acc[mi][ni][3] + by;
                if (OM == 0) {
                    float* C = (float*)Cv;
                    float2 ra = *(const float2*)&R[(size_t)r0 * N + c0];
                    float2 rb = *(const float2*)&R[(size_t)(r0 + 8) * N + c0];
                    *(float2*)&C[(size_t)r0 * N + c0]       = make_float2(v00 + ra.x, v01 + ra.y);
                    *(float2*)&C[(size_t)(r0 + 8) * N + c0] = make_float2(v10 + rb.x, v11 + rb.y);
                } else if (OM == 4) {
                    float* C = (float*)Cv;
                    *(float2*)&C[(size_t)r0 * N + c0]       = make_float2(v00, v01);
                    *(float2*)&C[(size_t)(r0 + 8) * N + c0] = make_float2(v10, v11);
                } else {
                    if (OM == 2) {
                        v00 = fmaxf(v00, 0.f); v01 = fmaxf(v01, 0.f);
                        v10 = fmaxf(v10, 0.f); v11 = fmaxf(v11, 0.f);
                    }
                    if (OM == 3 && c0 < Hd) {
                        v00 *= 0.125f; v01 *= 0.125f;
                        v10 *= 0.125f; v11 *= 0.125f;
                    }
                    unsigned* C = (unsigned*)Cv;
                    uint2 u0 = make_uint2(f2tf(v00), f2tf(v01));
                    uint2 u1 = make_uint2(f2tf(v10), f2tf(v11));
                    *(uint2*)&C[(size_t)r0 * N + c0]       = u0;
                    *(uint2*)&C[(size_t)(r0 + 8) * N + c0] = u1;
                }
            }
        }
    }
}

// ============================================================================
// Flash attention on tf32-bit inputs (q pre-scaled). Output: tf32 bits.
// ============================================================================
#define KSP 68
#define VSP 72
#define PSP 132
#define FLASH_SMEM ((2*128*KSP + 2*128*VSP + 128*PSP) * 4 + 256)

__global__ void __launch_bounds__(256, 1)
flash_attn(const unsigned* __restrict__ qkv,
           const unsigned char* __restrict__ mask,
           unsigned* __restrict__ ctx)
{
    extern __shared__ char smem_raw[];
    unsigned* Ks = (unsigned*)smem_raw;
    unsigned* Vs = Ks + 2*128*KSP;
    unsigned* Ps = Vs + 2*128*VSP;
    unsigned char* Ms = (unsigned char*)(Ps + 128*PSP);

    int bi = blockIdx.y;
    int b = bi >> 3, h = bi & 7;
    int qBase = blockIdx.x * 128;
    const unsigned* Qg = qkv + (size_t)b*Sd*QKVW + h*DKd;
    const unsigned* Kg = qkv + (size_t)b*Sd*QKVW + Hd   + h*DKd;
    const unsigned* Vg = qkv + (size_t)b*Sd*QKVW + 2*Hd + h*DKd;
    const unsigned char* mr = mask + (size_t)b*Sd;
    unsigned* Cg = ctx + (size_t)b*Sd*Hd + h*DKd;

    int tid = threadIdx.x;
    int wid = tid >> 5, lane = tid & 31;
    int g = lane >> 2, t = lane & 3;
    int wm = wid * 16;

    unsigned qf[8][4];
    {
        int r0 = qBase + wm + g, r1 = r0 + 8;
        #pragma unroll
        for (int kk = 0; kk < 8; kk++) {
            qf[kk][0] = Qg[(size_t)r0*QKVW + kk*8 + t];
            qf[kk][1] = Qg[(size_t)r1*QKVW + kk*8 + t];
            qf[kk][2] = Qg[(size_t)r0*QKVW + kk*8 + 4 + t];
            qf[kk][3] = Qg[(size_t)r1*QKVW + kk*8 + 4 + t];
        }
    }

    float m0 = -1e30f, m1 = -1e30f, l0 = 0.f, l1 = 0.f;
    float o[8][4];
    #pragma unroll
    for (int i = 0; i < 8; i++)
        #pragma unroll
        for (int r = 0; r < 4; r++) o[i][r] = 0.f;

    auto loadTile = [&](int kt, int buf) {
        unsigned* Ktile = Ks + buf*128*KSP;
        unsigned* Vtile = Vs + buf*128*VSP;
        #pragma unroll
        for (int i = 0; i < 8; i++) {
            int li = tid + i * 256;
            int r = li >> 4, cq = (li & 15) * 4;
            cpa16((unsigned)__cvta_generic_to_shared(&Ktile[r*KSP + cq]),
                  &Kg[(size_t)(kt*128 + r)*QKVW + cq]);
            cpa16((unsigned)__cvta_generic_to_shared(&Vtile[r*VSP + cq]),
                  &Vg[(size_t)(kt*128 + r)*QKVW + cq]);
        }
        if (tid < 32) {
            uchar4 mv = *(const uchar4*)&mr[kt*128 + tid*4];
            *(uchar4*)&Ms[buf*128 + tid*4] = mv;
        }
        cp_commit();
    };

    const int NT = Sd / 128;
    loadTile(0, 0);

    for (int kt = 0; kt < NT; kt++) {
        int buf = kt & 1;
        if (kt + 1 < NT) { loadTile(kt + 1, buf ^ 1); cp_wait<1>(); }
        else             { cp_wait<0>(); }
        __syncthreads();

        const unsigned* Ktile = Ks + buf*128*KSP;
        const unsigned* Vtile = Vs + buf*128*VSP;
        const unsigned char* Mt = Ms + buf*128;

        float s[16][4];
        #pragma unroll
        for (int ni = 0; ni < 16; ni++)
            #pragma unroll
            for (int r = 0; r < 4; r++) s[ni][r] = 0.f;

        #pragma unroll
        for (int kk = 0; kk < 8; kk++) {
            #pragma unroll
            for (int ni = 0; ni < 16; ni++) {
                int n = ni*8 + g;
                unsigned b0 = Ktile[n*KSP + kk*8 + t];
                unsigned b1 = Ktile[n*KSP + kk*8 + 4 + t];
                mma8(s[ni], qf[kk][0], qf[kk][1], qf[kk][2], qf[kk][3], b0, b1);
            }
        }

        float mt0 = -1e30f, mt1 = -1e30f;
        #pragma unroll
        for (int ni = 0; ni < 16; ni++) {
            int c = ni*8 + 2*t;
            if (Mt[c])     { s[ni][0] = -1e30f; s[ni][2] = -1e30f; }
            if (Mt[c + 1]) { s[ni][1] = -1e30f; s[ni][3] = -1e30f; }
            mt0 = fmaxf(mt0, fmaxf(s[ni][0], s[ni][1]));
            mt1 = fmaxf(mt1, fmaxf(s[ni][2], s[ni][3]));
        }
        mt0 = fmaxf(mt0, __shfl_xor_sync(0xffffffffu, mt0, 1));
        mt0 = fmaxf(mt0, __shfl_xor_sync(0xffffffffu, mt0, 2));
        mt1 = fmaxf(mt1, __shfl_xor_sync(0xffffffffu, mt1, 1));
        mt1 = fmaxf(mt1, __shfl_xor_sync(0xffffffffu, mt1, 2));

        float mn0 = fmaxf(m0, mt0), mn1 = fmaxf(m1, mt1);
        float c0 = __expf(m0 - mn0), c1 = __expf(m1 - mn1);
        m0 = mn0; m1 = mn1;

        float rs0 = 0.f, rs1 = 0.f;
        #pragma unroll
        for (int ni = 0; ni < 16; ni++) {
            float p0 = __expf(s[ni][0] - m0);
            float p1 = __expf(s[ni][1] - m0);
            float p2 = __expf(s[ni][2] - m1);
            float p3 = __expf(s[ni][3] - m1);
            rs0 += p0 + p1;
            rs1 += p2 + p3;
            int row = wm + g;
            int col = ni*8 + 2*t;
            Ps[row*PSP + col]       = f2tf(p0);
            Ps[row*PSP + col + 1]   = f2tf(p1);
            Ps[(row+8)*PSP + col]   = f2tf(p2);
            Ps[(row+8)*PSP + col+1] = f2tf(p3);
        }
        rs0 += __shfl_xor_sync(0xffffffffu, rs0, 1);
        rs0 += __shfl_xor_sync(0xffffffffu, rs0, 2);
        rs1 += __shfl_xor_sync(0xffffffffu, rs1, 1);
        rs1 += __shfl_xor_sync(0xffffffffu, rs1, 2);
        l0 = l0 * c0 + rs0;
        l1 = l1 * c1 + rs1;

        #pragma unroll
        for (int oni = 0; oni < 8; oni++) {
            o[oni][0] *= c0; o[oni][1] *= c0;
            o[oni][2] *= c1; o[oni][3] *= c1;
        }

        __syncwarp();

        #pragma unroll
        for (int kk = 0; kk < 16; kk++) {
            unsigned a0 = Ps[(wm + g)*PSP     + kk*8 + t];
            unsigned a1 = Ps[(wm + 8 + g)*PSP + kk*8 + t];
            unsigned a2 = Ps[(wm + g)*PSP     + kk*8 + 4 + t];
            unsigned a3 = Ps[(wm + 8 + g)*PSP + kk*8 + 4 + t];
            #pragma unroll
            for (int oni = 0; oni < 8; oni++) {
                unsigned b0 = Vtile[(kk*8 + t)*VSP     + oni*8 + g];
                unsigned b1 = Vtile[(kk*8 + 4 + t)*VSP + oni*8 + g];
                mma8(o[oni], a0, a1, a2, a3, b0, b1);
            }
        }
        __syncthreads();
    }

    float i0 = 1.f / l0, i1 = 1.f / l1;
    int r0 = qBase + wm + g, r1 = r0 + 8;
    #pragma unroll
    for (int oni = 0; oni < 8; oni++) {
        int c = oni*8 + 2*t;
        uint2 u0 = make_uint2(f2tf(o[oni][0] * i0), f2tf(o[oni][1] * i0));
        uint2 u1 = make_uint2(f2tf(o[oni][2] * i1), f2tf(o[oni][3] * i1));
        *(uint2*)&Cg[(size_t)r0*Hd + c] = u0;
        *(uint2*)&Cg[(size_t)r1*Hd + c] = u1;
    }
}

// ---------------- launch ----------------
extern "C" void kernel_launch(void* const* d_in, const int* in_sizes, int n_in,
                              void* d_out, int out_size)
{
    const int*           src  = (const int*)d_in[0];
    const unsigned char* mask = (const unsigned char*)d_in[1];
    const float* emb  = (const float*)d_in[2];
    const float* Wq   = (const float*)d_in[3];
    const float* bq   = (const float*)d_in[4];
    const float* Wk   = (const float*)d_in[5];
    const float* bk   = (const float*)d_in[6];
    const float* Wv   = (const float*)d_in[7];
    const float* bv   = (const float*)d_in[8];
    const float* Wo   = (const float*)d_in[9];
    const float* bo   = (const float*)d_in[10];
    const float* ln1g = (const float*)d_in[11];
    const float* ln1b = (const float*)d_in[12];
    const float* W1   = (const float*)d_in[13];
    const float* b1   = (const float*)d_in[14];
    const float* W2   = (const float*)d_in[15];
    const float* b2   = (const float*)d_in[16];
    const float* ln2g = (const float*)d_in[17];
    const float* ln2b = (const float*)d_in[18];
    const float* lnfg = (const float*)d_in[19];
    const float* lnfb = (const float*)d_in[20];
    const float* Wg   = (const float*)d_in[21];
    const float* bg   = (const float*)d_in[22];
    float* out = (float*)d_out;

    float *x;   unsigned *h, *qkv, *ctx, *ff;
    unsigned *wqkv, *wo, *w1, *w2, *wg;  float *bqkv;
    cudaGetSymbolAddress((void**)&x,    g_x);
    cudaGetSymbolAddress((void**)&h,    g_h);
    cudaGetSymbolAddress((void**)&qkv,  g_qkv);
    cudaGetSymbolAddress((void**)&ctx,  g_ctx);
    cudaGetSymbolAddress((void**)&ff,   g_ff);
    cudaGetSymbolAddress((void**)&wqkv, g_wqkv);
    cudaGetSymbolAddress((void**)&wo,   g_wo);
    cudaGetSymbolAddress((void**)&w1,   g_w1);
    cudaGetSymbolAddress((void**)&w2,   g_w2);
    cudaGetSymbolAddress((void**)&wg,   g_wg);
    cudaGetSymbolAddress((void**)&bqkv, g_bqkv);

    static bool attr_set = false;
    if (!attr_set) {
        cudaFuncSetAttribute(flash_attn,
                             cudaFuncAttributeMaxDynamicSharedMemorySize, FLASH_SMEM);
        cudaFuncSetAttribute(gemm_pk<0>,
                             cudaFuncAttributeMaxDynamicSharedMemorySize, GEMM_SMEM);
        cudaFuncSetAttribute(gemm_pk<2>,
                             cudaFuncAttributeMaxDynamicSharedMemorySize, GEMM_SMEM);
        cudaFuncSetAttribute(gemm_pk<3>,
                             cudaFuncAttributeMaxDynamicSharedMemorySize, GEMM_SMEM);
        cudaFuncSetAttribute(gemm_pk<4>,
                             cudaFuncAttributeMaxDynamicSharedMemorySize, GEMM_SMEM);
        attr_set = true;
    }

    // ---- prepack weights to tf32 bits ----
    pack_qkv_kernel<<<1184, 256>>>(Wq, Wk, Wv, wqkv);
    pack_bqkv_kernel<<<(Lx*QKVW + 255)/256, 256>>>(bq, bk, bv, bqkv);
    convert_kernel<<<1184, 256>>>(Wo, wo, Lx*Hd*Hd);
    convert_kernel<<<1184, 256>>>(W1, w1, Lx*Hd*FFd);
    convert_kernel<<<1184, 256>>>(W2, w2, Lx*FFd*Hd);
    convert_kernel<<<1184, 256>>>(Wg, wg, Hd*Vocab);

    embed_kernel<<<(Nt*Hd + 255)/256, 256>>>(src, emb, x);

    dim3 gQKV(QKVW/128, Nt/128);
    dim3 gH(Hd/128,  Nt/128);
    dim3 gF(FFd/128, Nt/128);
    dim3 gV((Vocab+127)/128, Nt/128);

    for (int l = 0; l < Lx; l++) {
        layernorm_kernel<<<Nt, 128>>>(x, ln1g + (size_t)l*Hd, ln1b + (size_t)l*Hd, h);

        gemm_pk<3><<<gQKV, 256, GEMM_SMEM>>>(h, wqkv + (size_t)l*Hd*QKVW, bqkv + (size_t)l*QKVW,
                                             nullptr, qkv, Nt, QKVW, Hd);

        flash_attn<<<dim3(Sd/128, Bd*NHd), 256, FLASH_SMEM>>>(qkv, mask, ctx);

        gemm_pk<0><<<gH, 256, GEMM_SMEM>>>(ctx, wo + (size_t)l*Hd*Hd, bo + (size_t)l*Hd,
                                           x, x, Nt, Hd, Hd);

        layernorm_kernel<<<Nt, 128>>>(x, ln2g + (size_t)l*Hd, ln2b + (size_t)l*Hd, h);

        gemm_pk<2><<<gF, 256, GEMM_SMEM>>>(h, w1 + (size_t)l*Hd*FFd, b1 + (size_t)l*FFd,
                                           nullptr, ff, Nt, FFd, Hd);
        gemm_pk<0><<<gH, 256, GEMM_SMEM>>>(ff, w2 + (size_t)l*FFd*Hd, b2 + (size_t)l*Hd,
                                           x, x, Nt, Hd, FFd);
    }

    layernorm_kernel<<<Nt, 128>>>(x, lnfg, lnfb, h);
    gemm_pk<4><<<gV, 256, GEMM_SMEM>>>(h, wg, bg, nullptr, out, Nt, Vocab, Hd);
}

// round 10
// speedup vs baseline: 1.7855x; 1.6812x over previous
#include <cuda_runtime.h>
#include <cuda_fp16.h>
#include <math.h>

// Problem constants
#define Lx  6
#define Hd  512
#define NHd 8
#define FFd 2048
#define Vocab 10000
#define Bd  4
#define Sd  2048
#define DKd 64
#define Nt  (Bd*Sd)     // 8192 tokens
#define QKVW 1536       // fused QKV width
#define QW2 768         // QKVW/2 words
#define HW2 256         // Hd/2 words
#define FW2 1024        // FFd/2 words

// ---------------- scratch (static device globals; no runtime alloc) ----------------
__device__ float    g_x[Nt*Hd];           // fp32 running activations
__device__ unsigned g_h[Nt*HW2];          // half2-packed LN output
__device__ unsigned g_qkv[Nt*QW2];        // half2-packed fused q|k|v
__device__ unsigned g_ctx[Nt*HW2];        // half2-packed attention output
__device__ unsigned g_ff[Nt*FW2];         // half2-packed FFN hidden
// prepacked fp16 weights: [K/2 words][N], word = half2(W[2k][n], W[2k+1][n])
__device__ unsigned g_wqkv[Lx*HW2*QKVW];
__device__ unsigned g_wo[Lx*HW2*Hd];
__device__ unsigned g_w1[Lx*HW2*FFd];
__device__ unsigned g_w2[Lx*FW2*Hd];
__device__ unsigned g_wg[HW2*Vocab];
__device__ float    g_bqkv[Lx*QKVW];

// ---------------- helpers ----------------
__device__ __forceinline__ unsigned pack2(float a, float b) {
    __half2 h2 = __floats2half2_rn(a, b);   // .x = low = a
    return *reinterpret_cast<unsigned*>(&h2);
}

__device__ __forceinline__ void mma16(float* c,
                                      unsigned a0, unsigned a1, unsigned a2, unsigned a3,
                                      unsigned b0, unsigned b1) {
    asm volatile(
        "mma.sync.aligned.m16n8k16.row.col.f32.f16.f16.f32 "
        "{%0,%1,%2,%3}, {%4,%5,%6,%7}, {%8,%9}, {%0,%1,%2,%3};"
        : "+f"(c[0]), "+f"(c[1]), "+f"(c[2]), "+f"(c[3])
        : "r"(a0), "r"(a1), "r"(a2), "r"(a3), "r"(b0), "r"(b1));
}

__device__ __forceinline__ void cpa16(unsigned dst, const void* src) {
    asm volatile("cp.async.ca.shared.global [%0], [%1], 16;" :: "r"(dst), "l"(src));
}
__device__ __forceinline__ void cpa16p(unsigned dst, const void* src, int bytes) {
    asm volatile("cp.async.ca.shared.global [%0], [%1], 16, %2;" :: "r"(dst), "l"(src), "r"(bytes));
}
__device__ __forceinline__ void cp_commit() { asm volatile("cp.async.commit_group;"); }
template<int N> __device__ __forceinline__ void cp_wait() {
    asm volatile("cp.async.wait_group %0;" :: "n"(N));
}

// ---------------- weight prepack: fp32 [rows][N] -> half2 [rows/2][N] ----------------
__global__ void conv_pack(const float* __restrict__ src,
                          unsigned* __restrict__ dst, int N, int totalWords)
{
    for (int w = blockIdx.x * blockDim.x + threadIdx.x;
         w < totalWords; w += gridDim.x * blockDim.x) {
        int r2 = w / N, n = w - r2 * N;
        dst[w] = pack2(src[(size_t)(2*r2)*N + n], src[(size_t)(2*r2+1)*N + n]);
    }
}

__global__ void pack_qkv_kernel(const float* __restrict__ Wq,
                                const float* __restrict__ Wk,
                                const float* __restrict__ Wv,
                                unsigned* __restrict__ dst)
{
    for (int idx = blockIdx.x * blockDim.x + threadIdx.x;
         idx < Lx*HW2*QKVW; idx += gridDim.x * blockDim.x) {
        int l = idx / (HW2*QKVW);
        int rem = idx - l * HW2*QKVW;
        int k2 = rem / QKVW;
        int n = rem - k2 * QKVW;
        const float* Wm; int nn;
        if (n < Hd)        { Wm = Wq; nn = n; }
        else if (n < 2*Hd) { Wm = Wk; nn = n - Hd; }
        else               { Wm = Wv; nn = n - 2*Hd; }
        float v0 = Wm[(size_t)l*Hd*Hd + (2*k2)*Hd + nn];
        float v1 = Wm[(size_t)l*Hd*Hd + (2*k2+1)*Hd + nn];
        dst[idx] = pack2(v0, v1);
    }
}

__global__ void pack_bqkv_kernel(const float* __restrict__ bq,
                                 const float* __restrict__ bk,
                                 const float* __restrict__ bv,
                                 float* __restrict__ dst)
{
    int idx = blockIdx.x * blockDim.x + threadIdx.x;
    if (idx >= Lx*QKVW) return;
    int l = idx / QKVW;
    int n = idx - l * QKVW;
    float val;
    if (n < Hd)        val = bq[l*Hd + n];
    else if (n < 2*Hd) val = bk[l*Hd + (n - Hd)];
    else               val = bv[l*Hd + (n - 2*Hd)];
    dst[idx] = val;
}

// ---------------- embedding + sinusoidal positional encoding ----------------
__global__ void embed_kernel(const int* __restrict__ src,
                             const float* __restrict__ emb,
                             float* __restrict__ x)
{
    int idx = blockIdx.x * blockDim.x + threadIdx.x;
    if (idx >= Nt*Hd) return;
    int n = idx >> 9;
    int c = idx & (Hd-1);
    int s = n & (Sd-1);
    int tok = src[n];
    int i2 = c & ~1;
    float div = expf(-(logf(10000.0f)/(float)Hd) * (float)i2);
    float ang = (float)s * div;
    float pe = (c & 1) ? cosf(ang) : sinf(ang);
    x[idx] = emb[(size_t)tok*Hd + c] + pe;
}

// ---------------- layernorm: fp32 in -> half2 words out ----------------
__global__ void layernorm_kernel(const float* __restrict__ x,
                                 const float* __restrict__ g,
                                 const float* __restrict__ b,
                                 unsigned* __restrict__ out)
{
    int row = blockIdx.x;
    int tid = threadIdx.x;
    const float* xr = x + (size_t)row*Hd;
    float4 v = *reinterpret_cast<const float4*>(xr + tid*4);

    __shared__ float red[4];
    __shared__ float red2[4];

    float s = v.x + v.y + v.z + v.w;
    #pragma unroll
    for (int o = 16; o > 0; o >>= 1) s += __shfl_xor_sync(0xffffffffu, s, o);
    if ((tid & 31) == 0) red[tid >> 5] = s;
    __syncthreads();
    float mean = (red[0] + red[1] + red[2] + red[3]) * (1.0f/(float)Hd);

    float dx = v.x - mean, dy = v.y - mean, dz = v.z - mean, dw = v.w - mean;
    float ss = dx*dx + dy*dy + dz*dz + dw*dw;
    #pragma unroll
    for (int o = 16; o > 0; o >>= 1) ss += __shfl_xor_sync(0xffffffffu, ss, o);
    if ((tid & 31) == 0) red2[tid >> 5] = ss;
    __syncthreads();
    float var = (red2[0] + red2[1] + red2[2] + red2[3]) * (1.0f/(float)Hd);
    float rstd = rsqrtf(var + 1e-5f);

    int c = tid*4;
    float4 gg = *reinterpret_cast<const float4*>(g + c);
    float4 bb = *reinterpret_cast<const float4*>(b + c);
    float o0 = dx*rstd*gg.x + bb.x;
    float o1 = dy*rstd*gg.y + bb.y;
    float o2 = dz*rstd*gg.z + bb.z;
    float o3 = dw*rstd*gg.w + bb.w;
    uint2 w2 = make_uint2(pack2(o0, o1), pack2(o2, o3));
    *reinterpret_cast<uint2*>(out + (size_t)row*HW2 + tid*2) = w2;
}

// ============================================================================
// fp16 GEMM: A [M][K2] half2 words (k-pairs), B [K2][N] half2 words.
// 128x128 tile, 32-k (16 words) per stage, 3-stage cp.async, m16n8k16.
// OUT modes: 0 = f32 + residual, 2 = half2+relu,
//            3 = half2 with cols<Hd scaled 0.125 (fused QKV), 4 = f32 plain
// ============================================================================
#define GKTW 16     // k-words per stage (32 k)
#define APAD 20
#define BPAD 136
#define GEMM_SMEM ((3*128*APAD + 3*GKTW*BPAD) * 4)

template<int OM>
__global__ void __launch_bounds__(256, 2)
gemm_hk(const unsigned* __restrict__ A,
        const unsigned* __restrict__ B,
        const float* __restrict__ bias,
        const float* __restrict__ R,
        void* __restrict__ Cv,
        int M, int N, int K2)
{
    extern __shared__ unsigned gsm[];
    unsigned* As = gsm;                 // [3][128][APAD]
    unsigned* Bs = gsm + 3*128*APAD;    // [3][GKTW][BPAD]

    int tid = threadIdx.x;
    int wid = tid >> 5, lane = tid & 31;
    int g = lane >> 2, t = lane & 3;
    int wm = (wid >> 2) * 64;
    int wn = (wid & 3) * 32;
    int rowBase = blockIdx.y * 128;
    int colBase = blockIdx.x * 128;

    float acc[4][4][4];
    #pragma unroll
    for (int mi = 0; mi < 4; mi++)
        #pragma unroll
        for (int ni = 0; ni < 4; ni++)
            #pragma unroll
            for (int r = 0; r < 4; r++) acc[mi][ni][r] = 0.0f;

    int nst = K2 / GKTW;

    auto loadStage = [&](int st, int k0w) {
        unsigned* Adst = As + st*128*APAD;
        unsigned* Bdst = Bs + st*GKTW*BPAD;
        #pragma unroll
        for (int i = 0; i < 2; i++) {
            int li = tid + i * 256;
            int r = li >> 2, kq = (li & 3) * 4;
            cpa16((unsigned)__cvta_generic_to_shared(&Adst[r*APAD + kq]),
                  &A[(size_t)(rowBase + r) * K2 + k0w + kq]);
        }
        #pragma unroll
        for (int i = 0; i < 2; i++) {
            int li = tid + i * 256;
            int r = li >> 5, cq = (li & 31) * 4;
            int gc = colBase + cq;
            cpa16p((unsigned)__cvta_generic_to_shared(&Bdst[r*BPAD + cq]),
                   &B[(size_t)(k0w + r) * N + gc], (gc + 4 <= N) ? 16 : 0);
        }
        cp_commit();
    };

    auto computeStage = [&](int st) {
        const unsigned* Asrc = As + st*128*APAD;
        const unsigned* Bsrc = Bs + st*GKTW*BPAD;
        #pragma unroll
        for (int kk2 = 0; kk2 < GKTW; kk2 += 8) {   // 2 x k16 chunks
            unsigned a[4][4], b[4][2];
            #pragma unroll
            for (int mi = 0; mi < 4; mi++) {
                int m = wm + mi * 16 + g;
                a[mi][0] = Asrc[m*APAD       + kk2 + t];
                a[mi][1] = Asrc[(m + 8)*APAD + kk2 + t];
                a[mi][2] = Asrc[m*APAD       + kk2 + 4 + t];
                a[mi][3] = Asrc[(m + 8)*APAD + kk2 + 4 + t];
            }
            #pragma unroll
            for (int ni = 0; ni < 4; ni++) {
                int n = wn + ni * 8 + g;
                b[ni][0] = Bsrc[(kk2 + t)*BPAD     + n];
                b[ni][1] = Bsrc[(kk2 + 4 + t)*BPAD + n];
            }
            #pragma unroll
            for (int mi = 0; mi < 4; mi++)
                #pragma unroll
                for (int ni = 0; ni < 4; ni++)
                    mma16(acc[mi][ni], a[mi][0], a[mi][1], a[mi][2], a[mi][3],
                          b[ni][0], b[ni][1]);
        }
    };

    loadStage(0, 0);
    if (nst > 1) loadStage(1, GKTW);

    for (int s = 0; s < nst; s++) {
        if (s + 1 < nst) cp_wait<1>(); else cp_wait<0>();
        __syncthreads();
        computeStage(s % 3);
        if (s + 2 < nst) loadStage((s + 2) % 3, (s + 2) * GKTW);
    }

    #pragma unroll
    for (int mi = 0; mi < 4; mi++) {
        #pragma unroll
        for (int ni = 0; ni < 4; ni++) {
            int r0 = rowBase + wm + mi * 16 + g;
            int c0 = colBase + wn + ni * 8 + 2 * t;   // even
            if (c0 < N) {
                float bx = bias[c0], by = bias[c0 + 1];
                float v00 = acc[mi][ni][0] + bx;
                float v01 = acc[mi][ni][1] + by;
                float v10 = acc[mi][ni][2] + bx;
                float v11 = acc[mi][ni][3] + by;
                if (OM == 0) {
                    float* C = (float*)Cv;
                    float2 ra = *(const float2*)&R[(size_t)r0 * N + c0];
                    float2 rb = *(const float2*)&R[(size_t)(r0 + 8) * N + c0];
                    *(float2*)&C[(size_t)r0 * N + c0]       = make_float2(v00 + ra.x, v01 + ra.y);
                    *(float2*)&C[(size_t)(r0 + 8) * N + c0] = make_float2(v10 + rb.x, v11 + rb.y);
                } else if (OM == 4) {
                    float* C = (float*)Cv;
                    *(float2*)&C[(size_t)r0 * N + c0]       = make_float2(v00, v01);
                    *(float2*)&C[(size_t)(r0 + 8) * N + c0] = make_float2(v10, v11);
                } else {
                    if (OM == 2) {
                        v00 = fmaxf(v00, 0.f); v01 = fmaxf(v01, 0.f);
                        v10 = fmaxf(v10, 0.f); v11 = fmaxf(v11, 0.f);
                    }
                    if (OM == 3 && c0 < Hd) {
                        v00 *= 0.125f; v01 *= 0.125f;
                        v10 *= 0.125f; v11 *= 0.125f;
                    }
                    unsigned* C = (unsigned*)Cv;
                    int n2 = N >> 1;
                    C[(size_t)r0 * n2 + (c0 >> 1)]       = pack2(v00, v01);
                    C[(size_t)(r0 + 8) * n2 + (c0 >> 1)] = pack2(v10, v11);
                }
            }
        }
    }
}

// ============================================================================
// fp16 flash attention. Q/K/V half2 words in g_qkv (q pre-scaled by 1/8).
// PV B-operand via explicit in-smem V transpose (no ldmatrix):
//   Vt[dim][key-word], word = half2(V[2kw][d], V[2kw+1][d])
// ============================================================================
#define KPAD 36
#define VPAD 36
#define VTP  68
#define PPAD 68
#define FLASH_SMEM ((2*128*KPAD + 2*128*VPAD + 64*VTP + 128*PPAD) * 4 + 256)

__global__ void __launch_bounds__(256, 1)
flash_attn(const unsigned* __restrict__ qkv,
           const unsigned char* __restrict__ mask,
           unsigned* __restrict__ ctx)
{
    extern __shared__ unsigned fsm[];
    unsigned* Ks = fsm;                         // [2][128][KPAD]
    unsigned* Vs = Ks + 2*128*KPAD;             // [2][128][VPAD] (raw [key][dim-word])
    unsigned* Vt = Vs + 2*128*VPAD;             // [64 dims][VTP key-words]
    unsigned* Ps = Vt + 64*VTP;                 // [128][PPAD] half2 words
    unsigned char* Ms = (unsigned char*)(Ps + 128*PPAD);   // 2*128

    int bi = blockIdx.y;
    int b = bi >> 3, h = bi & 7;
    int qBase = blockIdx.x * 128;
    const unsigned* Qg = qkv + (size_t)b*Sd*QW2 + h*(DKd/2);
    const unsigned* Kg = qkv + (size_t)b*Sd*QW2 + HW2     + h*(DKd/2);
    const unsigned* Vg = qkv + (size_t)b*Sd*QW2 + 2*HW2   + h*(DKd/2);
    const unsigned char* mr = mask + (size_t)b*Sd;
    unsigned* Cg = ctx + (size_t)b*Sd*HW2 + h*(DKd/2);

    int tid = threadIdx.x;
    int wid = tid >> 5, lane = tid & 31;
    int g = lane >> 2, t = lane & 3;
    int wm = wid * 16;

    // Q fragments: 4 chunks of k16 (DK=64)
    unsigned qf[4][4];
    {
        int r0 = qBase + wm + g, r1 = r0 + 8;
        #pragma unroll
        for (int c = 0; c < 4; c++) {
            qf[c][0] = Qg[(size_t)r0*QW2 + c*8 + t];
            qf[c][1] = Qg[(size_t)r1*QW2 + c*8 + t];
            qf[c][2] = Qg[(size_t)r0*QW2 + c*8 + 4 + t];
            qf[c][3] = Qg[(size_t)r1*QW2 + c*8 + 4 + t];
        }
    }

    float m0 = -1e30f, m1 = -1e30f, l0 = 0.f, l1 = 0.f;
    float o[8][4];
    #pragma unroll
    for (int i = 0; i < 8; i++)
        #pragma unroll
        for (int r = 0; r < 4; r++) o[i][r] = 0.f;

    auto loadTile = [&](int kt, int buf) {
        unsigned* Ktile = Ks + buf*128*KPAD;
        unsigned* Vtile = Vs + buf*128*VPAD;
        #pragma unroll
        for (int i = 0; i < 4; i++) {
            int li = tid + i * 256;
            int r = li >> 3, cq = (li & 7) * 4;
            cpa16((unsigned)__cvta_generic_to_shared(&Ktile[r*KPAD + cq]),
                  &Kg[(size_t)(kt*128 + r)*QW2 + cq]);
            cpa16((unsigned)__cvta_generic_to_shared(&Vtile[r*VPAD + cq]),
                  &Vg[(size_t)(kt*128 + r)*QW2 + cq]);
        }
        if (tid < 32) {
            uchar4 mv = *(const uchar4*)&mr[kt*128 + tid*4];
            *(uchar4*)&Ms[buf*128 + tid*4] = mv;
        }
        cp_commit();
    };

    const int NT = Sd / 128;   // 16
    loadTile(0, 0);

    for (int kt = 0; kt < NT; kt++) {
        int buf = kt & 1;
        if (kt + 1 < NT) { loadTile(kt + 1, buf ^ 1); cp_wait<1>(); }
        else             { cp_wait<0>(); }
        __syncthreads();

        const unsigned* Ktile = Ks + buf*128*KPAD;
        const unsigned* Vtile = Vs + buf*128*VPAD;
        const unsigned char* Mt = Ms + buf*128;

        // ---- transpose V tile: Vs[key][dim-word] -> Vt[dim][key-word] ----
        // cell c: kw = key-pair index (0..63), dw = dim-word (0..31)
        #pragma unroll
        for (int i = 0; i < 8; i++) {
            int c = tid + i * 256;
            int dw = c & 31, kw = c >> 5;
            unsigned w0 = Vtile[(2*kw)*VPAD + dw];
            unsigned w1 = Vtile[(2*kw+1)*VPAD + dw];
            Vt[(2*dw)*VTP + kw]   = __byte_perm(w0, w1, 0x5410);  // lows: dims 2dw
            Vt[(2*dw+1)*VTP + kw] = __byte_perm(w0, w1, 0x7632);  // highs: dims 2dw+1
        }

        // ---- S = Q K^T : 16 rows x 128 keys per warp ----
        float s[16][4];
        #pragma unroll
        for (int ni = 0; ni < 16; ni++)
            #pragma unroll
            for (int r = 0; r < 4; r++) s[ni][r] = 0.f;

        #pragma unroll
        for (int c = 0; c < 4; c++) {
            #pragma unroll
            for (int ni = 0; ni < 16; ni++) {
                int n = ni*8 + g;
                unsigned b0 = Ktile[n*KPAD + c*8 + t];
                unsigned b1 = Ktile[n*KPAD + c*8 + 4 + t];
                mma16(s[ni], qf[c][0], qf[c][1], qf[c][2], qf[c][3], b0, b1);
            }
        }

        // ---- mask + row max ----
        float mt0 = -1e30f, mt1 = -1e30f;
        #pragma unroll
        for (int ni = 0; ni < 16; ni++) {
            int c = ni*8 + 2*t;
            if (Mt[c])     { s[ni][0] = -1e30f; s[ni][2] = -1e30f; }
            if (Mt[c + 1]) { s[ni][1] = -1e30f; s[ni][3] = -1e30f; }
            mt0 = fmaxf(mt0, fmaxf(s[ni][0], s[ni][1]));
            mt1 = fmaxf(mt1, fmaxf(s[ni][2], s[ni][3]));
        }
        mt0 = fmaxf(mt0, __shfl_xor_sync(0xffffffffu, mt0, 1));
        mt0 = fmaxf(mt0, __shfl_xor_sync(0xffffffffu, mt0, 2));
        mt1 = fmaxf(mt1, __shfl_xor_sync(0xffffffffu, mt1, 1));
        mt1 = fmaxf(mt1, __shfl_xor_sync(0xffffffffu, mt1, 2));

        float mn0 = fmaxf(m0, mt0), mn1 = fmaxf(m1, mt1);
        float c0s = __expf(m0 - mn0), c1s = __expf(m1 - mn1);
        m0 = mn0; m1 = mn1;

        // ---- exp, row sums, write P (half2 pairs along key) ----
        float rs0 = 0.f, rs1 = 0.f;
        #pragma unroll
        for (int ni = 0; ni < 16; ni++) {
            float p0 = __expf(s[ni][0] - m0);
            float p1 = __expf(s[ni][1] - m0);
            float p2 = __expf(s[ni][2] - m1);
            float p3 = __expf(s[ni][3] - m1);
            rs0 += p0 + p1;
            rs1 += p2 + p3;
            int row = wm + g;
            int wrd = ni*4 + t;
            Ps[row*PPAD + wrd]     = pack2(p0, p1);
            Ps[(row+8)*PPAD + wrd] = pack2(p2, p3);
        }
        rs0 += __shfl_xor_sync(0xffffffffu, rs0, 1);
        rs0 += __shfl_xor_sync(0xffffffffu, rs0, 2);
        rs1 += __shfl_xor_sync(0xffffffffu, rs1, 1);
        rs1 += __shfl_xor_sync(0xffffffffu, rs1, 2);
        l0 = l0 * c0s + rs0;
        l1 = l1 * c1s + rs1;

        #pragma unroll
        for (int oni = 0; oni < 8; oni++) {
            o[oni][0] *= c0s; o[oni][1] *= c0s;
            o[oni][2] *= c1s; o[oni][3] *= c1s;
        }

        __syncthreads();   // Vt transpose writes visible to all warps

        // ---- O += P V : 8 chunks of 16 keys; B from Vt (k-pairs along key) ----
        #pragma unroll
        for (int kk = 0; kk < 8; kk++) {
            unsigned a0 = Ps[(wm + g)*PPAD     + kk*8 + t];
            unsigned a1 = Ps[(wm + 8 + g)*PPAD + kk*8 + t];
            unsigned a2 = Ps[(wm + g)*PPAD     + kk*8 + 4 + t];
            unsigned a3 = Ps[(wm + 8 + g)*PPAD + kk*8 + 4 + t];
            #pragma unroll
            for (int oni = 0; oni < 8; oni++) {
                int d = oni*8 + g;
                unsigned b0 = Vt[d*VTP + kk*8 + t];
                unsigned b1 = Vt[d*VTP + kk*8 + 4 + t];
                mma16(o[oni], a0, a1, a2, a3, b0, b1);
            }
        }
        __syncthreads();   // protect Ks/Vs/Vt/Ps reuse next iteration
    }

    // ---- epilogue: divide by l, pack half2, write ctx ----
    float i0 = 1.f / l0, i1 = 1.f / l1;
    int r0 = qBase + wm + g, r1 = r0 + 8;
    #pragma unroll
    for (int oni = 0; oni < 8; oni++) {
        int wrd = oni*4 + t;
        Cg[(size_t)r0*HW2 + wrd] = pack2(o[oni][0] * i0, o[oni][1] * i0);
        Cg[(size_t)r1*HW2 + wrd] = pack2(o[oni][2] * i1, o[oni][3] * i1);
    }
}

// ---------------- launch ----------------
extern "C" void kernel_launch(void* const* d_in, const int* in_sizes, int n_in,
                              void* d_out, int out_size)
{
    const int*           src  = (const int*)d_in[0];
    const unsigned char* mask = (const unsigned char*)d_in[1];
    const float* emb  = (const float*)d_in[2];
    const float* Wq   = (const float*)d_in[3];
    const float* bq   = (const float*)d_in[4];
    const float* Wk   = (const float*)d_in[5];
    const float* bk   = (const float*)d_in[6];
    const float* Wv   = (const float*)d_in[7];
    const float* bv   = (const float*)d_in[8];
    const float* Wo   = (const float*)d_in[9];
    const float* bo   = (const float*)d_in[10];
    const float* ln1g = (const float*)d_in[11];
    const float* ln1b = (const float*)d_in[12];
    const float* W1   = (const float*)d_in[13];
    const float* b1   = (const float*)d_in[14];
    const float* W2   = (const float*)d_in[15];
    const float* b2   = (const float*)d_in[16];
    const float* ln2g = (const float*)d_in[17];
    const float* ln2b = (const float*)d_in[18];
    const float* lnfg = (const float*)d_in[19];
    const float* lnfb = (const float*)d_in[20];
    const float* Wg   = (const float*)d_in[21];
    const float* bg   = (const float*)d_in[22];
    float* out = (float*)d_out;

    float *x;   unsigned *h, *qkv, *ctx, *ff;
    unsigned *wqkv, *wo, *w1, *w2, *wg;  float *bqkv;
    cudaGetSymbolAddress((void**)&x,    g_x);
    cudaGetSymbolAddress((void**)&h,    g_h);
    cudaGetSymbolAddress((void**)&qkv,  g_qkv);
    cudaGetSymbolAddress((void**)&ctx,  g_ctx);
    cudaGetSymbolAddress((void**)&ff,   g_ff);
    cudaGetSymbolAddress((void**)&wqkv, g_wqkv);
    cudaGetSymbolAddress((void**)&wo,   g_wo);
    cudaGetSymbolAddress((void**)&w1,   g_w1);
    cudaGetSymbolAddress((void**)&w2,   g_w2);
    cudaGetSymbolAddress((void**)&wg,   g_wg);
    cudaGetSymbolAddress((void**)&bqkv, g_bqkv);

    static bool attr_set = false;
    if (!attr_set) {
        cudaFuncSetAttribute(flash_attn,
                             cudaFuncAttributeMaxDynamicSharedMemorySize, FLASH_SMEM);
        cudaFuncSetAttribute(gemm_hk<0>,
                             cudaFuncAttributeMaxDynamicSharedMemorySize, GEMM_SMEM);
        cudaFuncSetAttribute(gemm_hk<2>,
                             cudaFuncAttributeMaxDynamicSharedMemorySize, GEMM_SMEM);
        cudaFuncSetAttribute(gemm_hk<3>,
                             cudaFuncAttributeMaxDynamicSharedMemorySize, GEMM_SMEM);
        cudaFuncSetAttribute(gemm_hk<4>,
                             cudaFuncAttributeMaxDynamicSharedMemorySize, GEMM_SMEM);
        attr_set = true;
    }

    // ---- prepack weights to half2 words ----
    pack_qkv_kernel<<<1184, 256>>>(Wq, Wk, Wv, wqkv);
    pack_bqkv_kernel<<<(Lx*QKVW + 255)/256, 256>>>(bq, bk, bv, bqkv);
    conv_pack<<<1184, 256>>>(Wo, wo, Hd,    Lx*HW2*Hd);
    conv_pack<<<1184, 256>>>(W1, w1, FFd,   Lx*HW2*FFd);
    conv_pack<<<1184, 256>>>(W2, w2, Hd,    Lx*FW2*Hd);
    conv_pack<<<1184, 256>>>(Wg, wg, Vocab, HW2*Vocab);

    embed_kernel<<<(Nt*Hd + 255)/256, 256>>>(src, emb, x);

    dim3 gQKV(QKVW/128, Nt/128);
    dim3 gH(Hd/128,  Nt/128);
    dim3 gF(FFd/128, Nt/128);
    dim3 gV((Vocab+127)/128, Nt/128);

    for (int l = 0; l < Lx; l++) {
        layernorm_kernel<<<Nt, 128>>>(x, ln1g + (size_t)l*Hd, ln1b + (size_t)l*Hd, h);

        // fused QKV (q cols pre-scaled by 1/8, half2 out)
        gemm_hk<3><<<gQKV, 256, GEMM_SMEM>>>(h, wqkv + (size_t)l*HW2*QKVW, bqkv + (size_t)l*QKVW,
                                             nullptr, qkv, Nt, QKVW, HW2);

        flash_attn<<<dim3(Sd/128, Bd*NHd), 256, FLASH_SMEM>>>(qkv, mask, ctx);

        // x = x + ctx @ Wo + bo
        gemm_hk<0><<<gH, 256, GEMM_SMEM>>>(ctx, wo + (size_t)l*HW2*Hd, bo + (size_t)l*Hd,
                                           x, x, Nt, Hd, HW2);

        layernorm_kernel<<<Nt, 128>>>(x, ln2g + (size_t)l*Hd, ln2b + (size_t)l*Hd, h);

        // ff = relu(h @ W1 + b1) (half2 out)
        gemm_hk<2><<<gF, 256, GEMM_SMEM>>>(h, w1 + (size_t)l*HW2*FFd, b1 + (size_t)l*FFd,
                                           nullptr, ff, Nt, FFd, HW2);
        // x = x + ff @ W2 + b2
        gemm_hk<0><<<gH, 256, GEMM_SMEM>>>(ff, w2 + (size_t)l*FW2*Hd, b2 + (size_t)l*Hd,
                                           x, x, Nt, Hd, FW2);
    }

    layernorm_kernel<<<Nt, 128>>>(x, lnfg, lnfb, h);
    gemm_hk<4><<<gV, 256, GEMM_SMEM>>>(h, wg, bg, nullptr, out, Nt, Vocab, HW2);
}

// round 12
// speedup vs baseline: 1.8732x; 1.0491x over previous
#include <cuda_runtime.h>
#include <cuda_fp16.h>
#include <math.h>

// Problem constants
#define Lx  6
#define Hd  512
#define NHd 8
#define FFd 2048
#define Vocab 10000
#define Bd  4
#define Sd  2048
#define DKd 64
#define Nt  (Bd*Sd)     // 8192 tokens
#define QKVW 1536       // fused QKV width
#define QW2 768         // QKVW/2 words
#define HW2 256         // Hd/2 words
#define FW2 1024        // FFd/2 words

// ---------------- scratch (static device globals; no runtime alloc) ----------------
__device__ float    g_x[Nt*Hd];           // fp32 running activations
__device__ unsigned g_h[Nt*HW2];          // half2-packed LN output
__device__ unsigned g_qkv[Nt*QW2];        // half2-packed fused q|k|v
__device__ unsigned g_ctx[Nt*HW2];        // half2-packed attention output
__device__ unsigned g_ff[Nt*FW2];         // half2-packed FFN hidden
// prepacked fp16 weights: [K/2 words][N], word = half2(W[2k][n], W[2k+1][n])
__device__ unsigned g_wqkv[Lx*HW2*QKVW];
__device__ unsigned g_wo[Lx*HW2*Hd];
__device__ unsigned g_w1[Lx*HW2*FFd];
__device__ unsigned g_w2[Lx*FW2*Hd];
__device__ unsigned g_wg[HW2*Vocab];
__device__ float    g_bqkv[Lx*QKVW];

// ---------------- helpers ----------------
__device__ __forceinline__ unsigned pack2(float a, float b) {
    __half2 h2 = __floats2half2_rn(a, b);   // .x = low = a
    return *reinterpret_cast<unsigned*>(&h2);
}

__device__ __forceinline__ void mma16(float* c,
                                      unsigned a0, unsigned a1, unsigned a2, unsigned a3,
                                      unsigned b0, unsigned b1) {
    asm volatile(
        "mma.sync.aligned.m16n8k16.row.col.f32.f16.f16.f32 "
        "{%0,%1,%2,%3}, {%4,%5,%6,%7}, {%8,%9}, {%0,%1,%2,%3};"
        : "+f"(c[0]), "+f"(c[1]), "+f"(c[2]), "+f"(c[3])
        : "r"(a0), "r"(a1), "r"(a2), "r"(a3), "r"(b0), "r"(b1));
}

__device__ __forceinline__ void cpa16(unsigned dst, const void* src) {
    asm volatile("cp.async.ca.shared.global [%0], [%1], 16;" :: "r"(dst), "l"(src));
}
__device__ __forceinline__ void cpa16p(unsigned dst, const void* src, int bytes) {
    asm volatile("cp.async.ca.shared.global [%0], [%1], 16, %2;" :: "r"(dst), "l"(src), "r"(bytes));
}
__device__ __forceinline__ void cp_commit() { asm volatile("cp.async.commit_group;"); }
template<int N> __device__ __forceinline__ void cp_wait() {
    asm volatile("cp.async.wait_group %0;" :: "n"(N));
}

// ---------------- weight prepack: fp32 [rows][N] -> half2 [rows/2][N] ----------------
__global__ void conv_pack(const float* __restrict__ src,
                          unsigned* __restrict__ dst, int N, int totalWords)
{
    for (int w = blockIdx.x * blockDim.x + threadIdx.x;
         w < totalWords; w += gridDim.x * blockDim.x) {
        int r2 = w / N, n = w - r2 * N;
        dst[w] = pack2(src[(size_t)(2*r2)*N + n], src[(size_t)(2*r2+1)*N + n]);
    }
}

__global__ void pack_qkv_kernel(const float* __restrict__ Wq,
                                const float* __restrict__ Wk,
                                const float* __restrict__ Wv,
                                unsigned* __restrict__ dst)
{
    for (int idx = blockIdx.x * blockDim.x + threadIdx.x;
         idx < Lx*HW2*QKVW; idx += gridDim.x * blockDim.x) {
        int l = idx / (HW2*QKVW);
        int rem = idx - l * HW2*QKVW;
        int k2 = rem / QKVW;
        int n = rem - k2 * QKVW;
        const float* Wm; int nn;
        if (n < Hd)        { Wm = Wq; nn = n; }
        else if (n < 2*Hd) { Wm = Wk; nn = n - Hd; }
        else               { Wm = Wv; nn = n - 2*Hd; }
        float v0 = Wm[(size_t)l*Hd*Hd + (2*k2)*Hd + nn];
        float v1 = Wm[(size_t)l*Hd*Hd + (2*k2+1)*Hd + nn];
        dst[idx] = pack2(v0, v1);
    }
}

__global__ void pack_bqkv_kernel(const float* __restrict__ bq,
                                 const float* __restrict__ bk,
                                 const float* __restrict__ bv,
                                 float* __restrict__ dst)
{
    int idx = blockIdx.x * blockDim.x + threadIdx.x;
    if (idx >= Lx*QKVW) return;
    int l = idx / QKVW;
    int n = idx - l * QKVW;
    float val;
    if (n < Hd)        val = bq[l*Hd + n];
    else if (n < 2*Hd) val = bk[l*Hd + (n - Hd)];
    else               val = bv[l*Hd + (n - 2*Hd)];
    dst[idx] = val;
}

// ---------------- embedding + sinusoidal positional encoding ----------------
__global__ void embed_kernel(const int* __restrict__ src,
                             const float* __restrict__ emb,
                             float* __restrict__ x)
{
    int idx = blockIdx.x * blockDim.x + threadIdx.x;
    if (idx >= Nt*Hd) return;
    int n = idx >> 9;
    int c = idx & (Hd-1);
    int s = n & (Sd-1);
    int tok = src[n];
    int i2 = c & ~1;
    float div = expf(-(logf(10000.0f)/(float)Hd) * (float)i2);
    float ang = (float)s * div;
    float pe = (c & 1) ? cosf(ang) : sinf(ang);
    x[idx] = emb[(size_t)tok*Hd + c] + pe;
}

// ---------------- layernorm: fp32 in -> half2 words out ----------------
__global__ void layernorm_kernel(const float* __restrict__ x,
                                 const float* __restrict__ g,
                                 const float* __restrict__ b,
                                 unsigned* __restrict__ out)
{
    int row = blockIdx.x;
    int tid = threadIdx.x;
    const float* xr = x + (size_t)row*Hd;
    float4 v = *reinterpret_cast<const float4*>(xr + tid*4);

    __shared__ float red[4];
    __shared__ float red2[4];

    float s = v.x + v.y + v.z + v.w;
    #pragma unroll
    for (int o = 16; o > 0; o >>= 1) s += __shfl_xor_sync(0xffffffffu, s, o);
    if ((tid & 31) == 0) red[tid >> 5] = s;
    __syncthreads();
    float mean = (red[0] + red[1] + red[2] + red[3]) * (1.0f/(float)Hd);

    float dx = v.x - mean, dy = v.y - mean, dz = v.z - mean, dw = v.w - mean;
    float ss = dx*dx + dy*dy + dz*dz + dw*dw;
    #pragma unroll
    for (int o = 16; o > 0; o >>= 1) ss += __shfl_xor_sync(0xffffffffu, ss, o);
    if ((tid & 31) == 0) red2[tid >> 5] = ss;
    __syncthreads();
    float var = (red2[0] + red2[1] + red2[2] + red2[3]) * (1.0f/(float)Hd);
    float rstd = rsqrtf(var + 1e-5f);

    int c = tid*4;
    float4 gg = *reinterpret_cast<const float4*>(g + c);
    float4 bb = *reinterpret_cast<const float4*>(b + c);
    float o0 = dx*rstd*gg.x + bb.x;
    float o1 = dy*rstd*gg.y + bb.y;
    float o2 = dz*rstd*gg.z + bb.z;
    float o3 = dw*rstd*gg.w + bb.w;
    uint2 w2 = make_uint2(pack2(o0, o1), pack2(o2, o3));
    *reinterpret_cast<uint2*>(out + (size_t)row*HW2 + tid*2) = w2;
}

// ============================================================================
// fp16 GEMM: A [M][K2] half2 words (k-pairs), B [K2][N] half2 words.
// 128x128 tile, 32-k (16 words) per stage, 3-stage cp.async, m16n8k16.
// OUT modes: 0 = f32 + residual, 2 = half2+relu,
//            3 = half2 with cols<Hd scaled 0.125 (fused QKV), 4 = f32 plain
// ============================================================================
#define GKTW 16     // k-words per stage (32 k)
#define APAD 20
#define BPAD 136
#define GEMM_SMEM ((3*128*APAD + 3*GKTW*BPAD) * 4)

template<int OM>
__global__ void __launch_bounds__(256, 2)
gemm_hk(const unsigned* __restrict__ A,
        const unsigned* __restrict__ B,
        const float* __restrict__ bias,
        const float* __restrict__ R,
        void* __restrict__ Cv,
        int M, int N, int K2)
{
    extern __shared__ unsigned gsm[];
    unsigned* As = gsm;                 // [3][128][APAD]
    unsigned* Bs = gsm + 3*128*APAD;    // [3][GKTW][BPAD]

    int tid = threadIdx.x;
    int wid = tid >> 5, lane = tid & 31;
    int g = lane >> 2, t = lane & 3;
    int wm = (wid >> 2) * 64;
    int wn = (wid & 3) * 32;
    int rowBase = blockIdx.y * 128;
    int colBase = blockIdx.x * 128;

    float acc[4][4][4];
    #pragma unroll
    for (int mi = 0; mi < 4; mi++)
        #pragma unroll
        for (int ni = 0; ni < 4; ni++)
            #pragma unroll
            for (int r = 0; r < 4; r++) acc[mi][ni][r] = 0.0f;

    int nst = K2 / GKTW;

    auto loadStage = [&](int st, int k0w) {
        unsigned* Adst = As + st*128*APAD;
        unsigned* Bdst = Bs + st*GKTW*BPAD;
        #pragma unroll
        for (int i = 0; i < 2; i++) {
            int li = tid + i * 256;
            int r = li >> 2, kq = (li & 3) * 4;
            cpa16((unsigned)__cvta_generic_to_shared(&Adst[r*APAD + kq]),
                  &A[(size_t)(rowBase + r) * K2 + k0w + kq]);
        }
        #pragma unroll
        for (int i = 0; i < 2; i++) {
            int li = tid + i * 256;
            int r = li >> 5, cq = (li & 31) * 4;
            int gc = colBase + cq;
            cpa16p((unsigned)__cvta_generic_to_shared(&Bdst[r*BPAD + cq]),
                   &B[(size_t)(k0w + r) * N + gc], (gc + 4 <= N) ? 16 : 0);
        }
        cp_commit();
    };

    auto computeStage = [&](int st) {
        const unsigned* Asrc = As + st*128*APAD;
        const unsigned* Bsrc = Bs + st*GKTW*BPAD;
        #pragma unroll
        for (int kk2 = 0; kk2 < GKTW; kk2 += 8) {   // 2 x k16 chunks
            unsigned a[4][4], b[4][2];
            #pragma unroll
            for (int mi = 0; mi < 4; mi++) {
                int m = wm + mi * 16 + g;
                a[mi][0] = Asrc[m*APAD       + kk2 + t];
                a[mi][1] = Asrc[(m + 8)*APAD + kk2 + t];
                a[mi][2] = Asrc[m*APAD       + kk2 + 4 + t];
                a[mi][3] = Asrc[(m + 8)*APAD + kk2 + 4 + t];
            }
            #pragma unroll
            for (int ni = 0; ni < 4; ni++) {
                int n = wn + ni * 8 + g;
                b[ni][0] = Bsrc[(kk2 + t)*BPAD     + n];
                b[ni][1] = Bsrc[(kk2 + 4 + t)*BPAD + n];
            }
            #pragma unroll
            for (int mi = 0; mi < 4; mi++)
                #pragma unroll
                for (int ni = 0; ni < 4; ni++)
                    mma16(acc[mi][ni], a[mi][0], a[mi][1], a[mi][2], a[mi][3],
                          b[ni][0], b[ni][1]);
        }
    };

    loadStage(0, 0);
    if (nst > 1) loadStage(1, GKTW);

    for (int s = 0; s < nst; s++) {
        if (s + 1 < nst) cp_wait<1>(); else cp_wait<0>();
        __syncthreads();
        computeStage(s % 3);
        if (s + 2 < nst) loadStage((s + 2) % 3, (s + 2) * GKTW);
    }

    #pragma unroll
    for (int mi = 0; mi < 4; mi++) {
        #pragma unroll
        for (int ni = 0; ni < 4; ni++) {
            int r0 = rowBase + wm + mi * 16 + g;
            int c0 = colBase + wn + ni * 8 + 2 * t;   // even
            if (c0 < N) {
                float bx = bias[c0], by = bias[c0 + 1];
                float v00 = acc[mi][ni][0] + bx;
                float v01 = acc[mi][ni][1] + by;
                float v10 = acc[mi][ni][2] + bx;
                float v11 = acc[mi][ni][3] + by;
                if (OM == 0) {
                    float* C = (float*)Cv;
                    float2 ra = *(const float2*)&R[(size_t)r0 * N + c0];
                    float2 rb = *(const float2*)&R[(size_t)(r0 + 8) * N + c0];
                    *(float2*)&C[(size_t)r0 * N + c0]       = make_float2(v00 + ra.x, v01 + ra.y);
                    *(float2*)&C[(size_t)(r0 + 8) * N + c0] = make_float2(v10 + rb.x, v11 + rb.y);
                } else if (OM == 4) {
                    float* C = (float*)Cv;
                    *(float2*)&C[(size_t)r0 * N + c0]       = make_float2(v00, v01);
                    *(float2*)&C[(size_t)(r0 + 8) * N + c0] = make_float2(v10, v11);
                } else {
                    if (OM == 2) {
                        v00 = fmaxf(v00, 0.f); v01 = fmaxf(v01, 0.f);
                        v10 = fmaxf(v10, 0.f); v11 = fmaxf(v11, 0.f);
                    }
                    if (OM == 3 && c0 < Hd) {
                        v00 *= 0.125f; v01 *= 0.125f;
                        v10 *= 0.125f; v11 *= 0.125f;
                    }
                    unsigned* C = (unsigned*)Cv;
                    int n2 = N >> 1;
                    C[(size_t)r0 * n2 + (c0 >> 1)]       = pack2(v00, v01);
                    C[(size_t)(r0 + 8) * n2 + (c0 >> 1)] = pack2(v10, v11);
                }
            }
        }
    }
}

// ============================================================================
// fp16 flash attention. Q/K/V half2 words in g_qkv (q pre-scaled by 1/8).
// P kept in registers: S-accumulator fragments are repacked in-place into
// PV A-operand fragments (bit-identical mapping to the former smem path).
// PV B-operand via explicit in-smem V transpose.
// ============================================================================
#define KPAD 36
#define VPAD 36
#define VTP  68
#define FLASH_SMEM ((2*128*KPAD + 2*128*VPAD + 64*VTP) * 4 + 256)

__global__ void __launch_bounds__(256, 1)
flash_attn(const unsigned* __restrict__ qkv,
           const unsigned char* __restrict__ mask,
           unsigned* __restrict__ ctx)
{
    extern __shared__ unsigned fsm[];
    unsigned* Ks = fsm;                         // [2][128][KPAD]
    unsigned* Vs = Ks + 2*128*KPAD;             // [2][128][VPAD] (raw [key][dim-word])
    unsigned* Vt = Vs + 2*128*VPAD;             // [64 dims][VTP key-words]
    unsigned char* Ms = (unsigned char*)(Vt + 64*VTP);   // 2*128

    int bi = blockIdx.y;
    int b = bi >> 3, h = bi & 7;
    int qBase = blockIdx.x * 128;
    const unsigned* Qg = qkv + (size_t)b*Sd*QW2 + h*(DKd/2);
    const unsigned* Kg = qkv + (size_t)b*Sd*QW2 + HW2     + h*(DKd/2);
    const unsigned* Vg = qkv + (size_t)b*Sd*QW2 + 2*HW2   + h*(DKd/2);
    const unsigned char* mr = mask + (size_t)b*Sd;
    unsigned* Cg = ctx + (size_t)b*Sd*HW2 + h*(DKd/2);

    int tid = threadIdx.x;
    int wid = tid >> 5, lane = tid & 31;
    int g = lane >> 2, t = lane & 3;
    int wm = wid * 16;

    // Q fragments: 4 chunks of k16 (DK=64)
    unsigned qf[4][4];
    {
        int r0 = qBase + wm + g, r1 = r0 + 8;
        #pragma unroll
        for (int c = 0; c < 4; c++) {
            qf[c][0] = Qg[(size_t)r0*QW2 + c*8 + t];
            qf[c][1] = Qg[(size_t)r1*QW2 + c*8 + t];
            qf[c][2] = Qg[(size_t)r0*QW2 + c*8 + 4 + t];
            qf[c][3] = Qg[(size_t)r1*QW2 + c*8 + 4 + t];
        }
    }

    float m0 = -1e30f, m1 = -1e30f, l0 = 0.f, l1 = 0.f;
    float o[8][4];
    #pragma unroll
    for (int i = 0; i < 8; i++)
        #pragma unroll
        for (int r = 0; r < 4; r++) o[i][r] = 0.f;

    auto loadTile = [&](int kt, int buf) {
        unsigned* Ktile = Ks + buf*128*KPAD;
        unsigned* Vtile = Vs + buf*128*VPAD;
        #pragma unroll
        for (int i = 0; i < 4; i++) {
            int li = tid + i * 256;
            int r = li >> 3, cq = (li & 7) * 4;
            cpa16((unsigned)__cvta_generic_to_shared(&Ktile[r*KPAD + cq]),
                  &Kg[(size_t)(kt*128 + r)*QW2 + cq]);
            cpa16((unsigned)__cvta_generic_to_shared(&Vtile[r*VPAD + cq]),
                  &Vg[(size_t)(kt*128 + r)*QW2 + cq]);
        }
        if (tid < 32) {
            uchar4 mv = *(const uchar4*)&mr[kt*128 + tid*4];
            *(uchar4*)&Ms[buf*128 + tid*4] = mv;
        }
        cp_commit();
    };

    const int NT = Sd / 128;   // 16
    loadTile(0, 0);

    for (int kt = 0; kt < NT; kt++) {
        int buf = kt & 1;
        if (kt + 1 < NT) { loadTile(kt + 1, buf ^ 1); cp_wait<1>(); }
        else             { cp_wait<0>(); }
        __syncthreads();

        const unsigned* Ktile = Ks + buf*128*KPAD;
        const unsigned* Vtile = Vs + buf*128*VPAD;
        const unsigned char* Mt = Ms + buf*128;

        // ---- transpose V tile: Vs[key][dim-word] -> Vt[dim][key-word] ----
        #pragma unroll
        for (int i = 0; i < 8; i++) {
            int c = tid + i * 256;
            int dw = c & 31, kw = c >> 5;
            unsigned w0 = Vtile[(2*kw)*VPAD + dw];
            unsigned w1 = Vtile[(2*kw+1)*VPAD + dw];
            Vt[(2*dw)*VTP + kw]   = __byte_perm(w0, w1, 0x5410);  // lows: dims 2dw
            Vt[(2*dw+1)*VTP + kw] = __byte_perm(w0, w1, 0x7632);  // highs: dims 2dw+1
        }

        // ---- S = Q K^T : 16 rows x 128 keys per warp ----
        float s[16][4];
        #pragma unroll
        for (int ni = 0; ni < 16; ni++)
            #pragma unroll
            for (int r = 0; r < 4; r++) s[ni][r] = 0.f;

        #pragma unroll
        for (int c = 0; c < 4; c++) {
            #pragma unroll
            for (int ni = 0; ni < 16; ni++) {
                int n = ni*8 + g;
                unsigned b0 = Ktile[n*KPAD + c*8 + t];
                unsigned b1 = Ktile[n*KPAD + c*8 + 4 + t];
                mma16(s[ni], qf[c][0], qf[c][1], qf[c][2], qf[c][3], b0, b1);
            }
        }

        // ---- mask + row max ----
        float mt0 = -1e30f, mt1 = -1e30f;
        #pragma unroll
        for (int ni = 0; ni < 16; ni++) {
            int c = ni*8 + 2*t;
            if (Mt[c])     { s[ni][0] = -1e30f; s[ni][2] = -1e30f; }
            if (Mt[c + 1]) { s[ni][1] = -1e30f; s[ni][3] = -1e30f; }
            mt0 = fmaxf(mt0, fmaxf(s[ni][0], s[ni][1]));
            mt1 = fmaxf(mt1, fmaxf(s[ni][2], s[ni][3]));
        }
        mt0 = fmaxf(mt0, __shfl_xor_sync(0xffffffffu, mt0, 1));
        mt0 = fmaxf(mt0, __shfl_xor_sync(0xffffffffu, mt0, 2));
        mt1 = fmaxf(mt1, __shfl_xor_sync(0xffffffffu, mt1, 1));
        mt1 = fmaxf(mt1, __shfl_xor_sync(0xffffffffu, mt1, 2));

        float mn0 = fmaxf(m0, mt0), mn1 = fmaxf(m1, mt1);
        float c0s = __expf(m0 - mn0), c1s = __expf(m1 - mn1);
        m0 = mn0; m1 = mn1;

        // ---- exp in-place + row sums (P stays in registers) ----
        float rs0 = 0.f, rs1 = 0.f;
        #pragma unroll
        for (int ni = 0; ni < 16; ni++) {
            s[ni][0] = __expf(s[ni][0] - m0);
            s[ni][1] = __expf(s[ni][1] - m0);
            s[ni][2] = __expf(s[ni][2] - m1);
            s[ni][3] = __expf(s[ni][3] - m1);
            rs0 += s[ni][0] + s[ni][1];
            rs1 += s[ni][2] + s[ni][3];
        }
        rs0 += __shfl_xor_sync(0xffffffffu, rs0, 1);
        rs0 += __shfl_xor_sync(0xffffffffu, rs0, 2);
        rs1 += __shfl_xor_sync(0xffffffffu, rs1, 1);
        rs1 += __shfl_xor_sync(0xffffffffu, rs1, 2);
        l0 = l0 * c0s + rs0;
        l1 = l1 * c1s + rs1;

        #pragma unroll
        for (int oni = 0; oni < 8; oni++) {
            o[oni][0] *= c0s; o[oni][1] *= c0s;
            o[oni][2] *= c1s; o[oni][3] *= c1s;
        }

        __syncthreads();   // Vt transpose writes visible to all warps

        // ---- O += P V : A-frags packed directly from S registers ----
        // a0 = keys (2kk)*8+2t,+1 row g  == pack2(s[2kk][0], s[2kk][1])
        // a1 = same keys row g+8        == pack2(s[2kk][2], s[2kk][3])
        // a2 = keys (2kk+1)*8+2t,+1 row g; a3 = row g+8
        #pragma unroll
        for (int kk = 0; kk < 8; kk++) {
            unsigned a0 = pack2(s[2*kk][0],   s[2*kk][1]);
            unsigned a1 = pack2(s[2*kk][2],   s[2*kk][3]);
            unsigned a2 = pack2(s[2*kk+1][0], s[2*kk+1][1]);
            unsigned a3 = pack2(s[2*kk+1][2], s[2*kk+1][3]);
            #pragma unroll
            for (int oni = 0; oni < 8; oni++) {
                int d = oni*8 + g;
                unsigned b0 = Vt[d*VTP + kk*8 + t];
                unsigned b1 = Vt[d*VTP + kk*8 + 4 + t];
                mma16(o[oni], a0, a1, a2, a3, b0, b1);
            }
        }
        __syncthreads();   // protect Ks/Vs/Vt reuse next iteration
    }

    // ---- epilogue: divide by l, pack half2, write ctx ----
    float i0 = 1.f / l0, i1 = 1.f / l1;
    int r0 = qBase + wm + g, r1 = r0 + 8;
    #pragma unroll
    for (int oni = 0; oni < 8; oni++) {
        int wrd = oni*4 + t;
        Cg[(size_t)r0*HW2 + wrd] = pack2(o[oni][0] * i0, o[oni][1] * i0);
        Cg[(size_t)r1*HW2 + wrd] = pack2(o[oni][2] * i1, o[oni][3] * i1);
    }
}

// ---------------- launch ----------------
extern "C" void kernel_launch(void* const* d_in, const int* in_sizes, int n_in,
                              void* d_out, int out_size)
{
    const int*           src  = (const int*)d_in[0];
    const unsigned char* mask = (const unsigned char*)d_in[1];
    const float* emb  = (const float*)d_in[2];
    const float* Wq   = (const float*)d_in[3];
    const float* bq   = (const float*)d_in[4];
    const float* Wk   = (const float*)d_in[5];
    const float* bk   = (const float*)d_in[6];
    const float* Wv   = (const float*)d_in[7];
    const float* bv   = (const float*)d_in[8];
    const float* Wo   = (const float*)d_in[9];
    const float* bo   = (const float*)d_in[10];
    const float* ln1g = (const float*)d_in[11];
    const float* ln1b = (const float*)d_in[12];
    const float* W1   = (const float*)d_in[13];
    const float* b1   = (const float*)d_in[14];
    const float* W2   = (const float*)d_in[15];
    const float* b2   = (const float*)d_in[16];
    const float* ln2g = (const float*)d_in[17];
    const float* ln2b = (const float*)d_in[18];
    const float* lnfg = (const float*)d_in[19];
    const float* lnfb = (const float*)d_in[20];
    const float* Wg   = (const float*)d_in[21];
    const float* bg   = (const float*)d_in[22];
    float* out = (float*)d_out;

    float *x;   unsigned *h, *qkv, *ctx, *ff;
    unsigned *wqkv, *wo, *w1, *w2, *wg;  float *bqkv;
    cudaGetSymbolAddress((void**)&x,    g_x);
    cudaGetSymbolAddress((void**)&h,    g_h);
    cudaGetSymbolAddress((void**)&qkv,  g_qkv);
    cudaGetSymbolAddress((void**)&ctx,  g_ctx);
    cudaGetSymbolAddress((void**)&ff,   g_ff);
    cudaGetSymbolAddress((void**)&wqkv, g_wqkv);
    cudaGetSymbolAddress((void**)&wo,   g_wo);
    cudaGetSymbolAddress((void**)&w1,   g_w1);
    cudaGetSymbolAddress((void**)&w2,   g_w2);
    cudaGetSymbolAddress((void**)&wg,   g_wg);
    cudaGetSymbolAddress((void**)&bqkv, g_bqkv);

    static bool attr_set = false;
    if (!attr_set) {
        cudaFuncSetAttribute(flash_attn,
                             cudaFuncAttributeMaxDynamicSharedMemorySize, FLASH_SMEM);
        cudaFuncSetAttribute(gemm_hk<0>,
                             cudaFuncAttributeMaxDynamicSharedMemorySize, GEMM_SMEM);
        cudaFuncSetAttribute(gemm_hk<2>,
                             cudaFuncAttributeMaxDynamicSharedMemorySize, GEMM_SMEM);
        cudaFuncSetAttribute(gemm_hk<3>,
                             cudaFuncAttributeMaxDynamicSharedMemorySize, GEMM_SMEM);
        cudaFuncSetAttribute(gemm_hk<4>,
                             cudaFuncAttributeMaxDynamicSharedMemorySize, GEMM_SMEM);
        attr_set = true;
    }

    // ---- prepack weights to half2 words ----
    pack_qkv_kernel<<<1184, 256>>>(Wq, Wk, Wv, wqkv);
    pack_bqkv_kernel<<<(Lx*QKVW + 255)/256, 256>>>(bq, bk, bv, bqkv);
    conv_pack<<<1184, 256>>>(Wo, wo, Hd,    Lx*HW2*Hd);
    conv_pack<<<1184, 256>>>(W1, w1, FFd,   Lx*HW2*FFd);
    conv_pack<<<1184, 256>>>(W2, w2, Hd,    Lx*FW2*Hd);
    conv_pack<<<1184, 256>>>(Wg, wg, Vocab, HW2*Vocab);

    embed_kernel<<<(Nt*Hd + 255)/256, 256>>>(src, emb, x);

    dim3 gQKV(QKVW/128, Nt/128);
    dim3 gH(Hd/128,  Nt/128);
    dim3 gF(FFd/128, Nt/128);
    dim3 gV((Vocab+127)/128, Nt/128);

    for (int l = 0; l < Lx; l++) {
        layernorm_kernel<<<Nt, 128>>>(x, ln1g + (size_t)l*Hd, ln1b + (size_t)l*Hd, h);

        // fused QKV (q cols pre-scaled by 1/8, half2 out)
        gemm_hk<3><<<gQKV, 256, GEMM_SMEM>>>(h, wqkv + (size_t)l*HW2*QKVW, bqkv + (size_t)l*QKVW,
                                             nullptr, qkv, Nt, QKVW, HW2);

        flash_attn<<<dim3(Sd/128, Bd*NHd), 256, FLASH_SMEM>>>(qkv, mask, ctx);

        // x = x + ctx @ Wo + bo
        gemm_hk<0><<<gH, 256, GEMM_SMEM>>>(ctx, wo + (size_t)l*HW2*Hd, bo + (size_t)l*Hd,
                                           x, x, Nt, Hd, HW2);

        layernorm_kernel<<<Nt, 128>>>(x, ln2g + (size_t)l*Hd, ln2b + (size_t)l*Hd, h);

        // ff = relu(h @ W1 + b1) (half2 out)
        gemm_hk<2><<<gF, 256, GEMM_SMEM>>>(h, w1 + (size_t)l*HW2*FFd, b1 + (size_t)l*FFd,
                                           nullptr, ff, Nt, FFd, HW2);
        // x = x + ff @ W2 + b2
        gemm_hk<0><<<gH, 256, GEMM_SMEM>>>(ff, w2 + (size_t)l*FW2*Hd, b2 + (size_t)l*Hd,
                                           x, x, Nt, Hd, FW2);
    }

    layernorm_kernel<<<Nt, 128>>>(x, lnfg, lnfb, h);
    gemm_hk<4><<<gV, 256, GEMM_SMEM>>>(h, wg, bg, nullptr, out, Nt, Vocab, HW2);
}

// round 13
// speedup vs baseline: 1.9201x; 1.0251x over previous
#include <cuda_runtime.h>
#include <cuda_fp16.h>
#include <math.h>

// Problem constants
#define Lx  6
#define Hd  512
#define NHd 8
#define FFd 2048
#define Vocab 10000
#define Bd  4
#define Sd  2048
#define DKd 64
#define Nt  (Bd*Sd)     // 8192 tokens
#define QKVW 1536       // fused QKV width
#define QW2 768         // QKVW/2 words
#define HW2 256         // Hd/2 words
#define FW2 1024        // FFd/2 words

// ---------------- scratch (static device globals; no runtime alloc) ----------------
__device__ float    g_x[Nt*Hd];           // fp32 running activations
__device__ unsigned g_h[Nt*HW2];          // half2-packed LN output
__device__ unsigned g_qkv[Nt*QW2];        // half2-packed fused q|k|v
__device__ unsigned g_ctx[Nt*HW2];        // half2-packed attention output
__device__ unsigned g_ff[Nt*FW2];         // half2-packed FFN hidden
// prepacked fp16 weights: [K/2 words][N], word = half2(W[2k][n], W[2k+1][n])
__device__ unsigned g_wqkv[Lx*HW2*QKVW];
__device__ unsigned g_wo[Lx*HW2*Hd];
__device__ unsigned g_w1[Lx*HW2*FFd];
__device__ unsigned g_w2[Lx*FW2*Hd];
__device__ unsigned g_wg[HW2*Vocab];
__device__ float    g_bqkv[Lx*QKVW];

// ---------------- helpers ----------------
__device__ __forceinline__ unsigned pack2(float a, float b) {
    __half2 h2 = __floats2half2_rn(a, b);   // .x = low = a
    return *reinterpret_cast<unsigned*>(&h2);
}

__device__ __forceinline__ void mma16(float* c,
                                      unsigned a0, unsigned a1, unsigned a2, unsigned a3,
                                      unsigned b0, unsigned b1) {
    asm volatile(
        "mma.sync.aligned.m16n8k16.row.col.f32.f16.f16.f32 "
        "{%0,%1,%2,%3}, {%4,%5,%6,%7}, {%8,%9}, {%0,%1,%2,%3};"
        : "+f"(c[0]), "+f"(c[1]), "+f"(c[2]), "+f"(c[3])
        : "r"(a0), "r"(a1), "r"(a2), "r"(a3), "r"(b0), "r"(b1));
}

__device__ __forceinline__ void cpa16(unsigned dst, const void* src) {
    asm volatile("cp.async.ca.shared.global [%0], [%1], 16;" :: "r"(dst), "l"(src));
}
__device__ __forceinline__ void cpa16p(unsigned dst, const void* src, int bytes) {
    asm volatile("cp.async.ca.shared.global [%0], [%1], 16, %2;" :: "r"(dst), "l"(src), "r"(bytes));
}
__device__ __forceinline__ void cp_commit() { asm volatile("cp.async.commit_group;"); }
template<int N> __device__ __forceinline__ void cp_wait() {
    asm volatile("cp.async.wait_group %0;" :: "n"(N));
}

// ---------------- weight prepack: fp32 [rows][N] -> half2 [rows/2][N] ----------------
__global__ void conv_pack(const float* __restrict__ src,
                          unsigned* __restrict__ dst, int N, int totalWords)
{
    for (int w = blockIdx.x * blockDim.x + threadIdx.x;
         w < totalWords; w += gridDim.x * blockDim.x) {
        int r2 = w / N, n = w - r2 * N;
        dst[w] = pack2(src[(size_t)(2*r2)*N + n], src[(size_t)(2*r2+1)*N + n]);
    }
}

__global__ void pack_qkv_kernel(const float* __restrict__ Wq,
                                const float* __restrict__ Wk,
                                const float* __restrict__ Wv,
                                unsigned* __restrict__ dst)
{
    for (int idx = blockIdx.x * blockDim.x + threadIdx.x;
         idx < Lx*HW2*QKVW; idx += gridDim.x * blockDim.x) {
        int l = idx / (HW2*QKVW);
        int rem = idx - l * HW2*QKVW;
        int k2 = rem / QKVW;
        int n = rem - k2 * QKVW;
        const float* Wm; int nn;
        if (n < Hd)        { Wm = Wq; nn = n; }
        else if (n < 2*Hd) { Wm = Wk; nn = n - Hd; }
        else               { Wm = Wv; nn = n - 2*Hd; }
        float v0 = Wm[(size_t)l*Hd*Hd + (2*k2)*Hd + nn];
        float v1 = Wm[(size_t)l*Hd*Hd + (2*k2+1)*Hd + nn];
        dst[idx] = pack2(v0, v1);
    }
}

__global__ void pack_bqkv_kernel(const float* __restrict__ bq,
                                 const float* __restrict__ bk,
                                 const float* __restrict__ bv,
                                 float* __restrict__ dst)
{
    int idx = blockIdx.x * blockDim.x + threadIdx.x;
    if (idx >= Lx*QKVW) return;
    int l = idx / QKVW;
    int n = idx - l * QKVW;
    float val;
    if (n < Hd)        val = bq[l*Hd + n];
    else if (n < 2*Hd) val = bk[l*Hd + (n - Hd)];
    else               val = bv[l*Hd + (n - 2*Hd)];
    dst[idx] = val;
}

// ---------------- embedding + sinusoidal positional encoding ----------------
__global__ void embed_kernel(const int* __restrict__ src,
                             const float* __restrict__ emb,
                             float* __restrict__ x)
{
    int idx = blockIdx.x * blockDim.x + threadIdx.x;
    if (idx >= Nt*Hd) return;
    int n = idx >> 9;
    int c = idx & (Hd-1);
    int s = n & (Sd-1);
    int tok = src[n];
    int i2 = c & ~1;
    float div = expf(-(logf(10000.0f)/(float)Hd) * (float)i2);
    float ang = (float)s * div;
    float pe = (c & 1) ? cosf(ang) : sinf(ang);
    x[idx] = emb[(size_t)tok*Hd + c] + pe;
}

// ---------------- layernorm: fp32 in -> half2 words out ----------------
__global__ void layernorm_kernel(const float* __restrict__ x,
                                 const float* __restrict__ g,
                                 const float* __restrict__ b,
                                 unsigned* __restrict__ out)
{
    int row = blockIdx.x;
    int tid = threadIdx.x;
    const float* xr = x + (size_t)row*Hd;
    float4 v = *reinterpret_cast<const float4*>(xr + tid*4);

    __shared__ float red[4];
    __shared__ float red2[4];

    float s = v.x + v.y + v.z + v.w;
    #pragma unroll
    for (int o = 16; o > 0; o >>= 1) s += __shfl_xor_sync(0xffffffffu, s, o);
    if ((tid & 31) == 0) red[tid >> 5] = s;
    __syncthreads();
    float mean = (red[0] + red[1] + red[2] + red[3]) * (1.0f/(float)Hd);

    float dx = v.x - mean, dy = v.y - mean, dz = v.z - mean, dw = v.w - mean;
    float ss = dx*dx + dy*dy + dz*dz + dw*dw;
    #pragma unroll
    for (int o = 16; o > 0; o >>= 1) ss += __shfl_xor_sync(0xffffffffu, ss, o);
    if ((tid & 31) == 0) red2[tid >> 5] = ss;
    __syncthreads();
    float var = (red2[0] + red2[1] + red2[2] + red2[3]) * (1.0f/(float)Hd);
    float rstd = rsqrtf(var + 1e-5f);

    int c = tid*4;
    float4 gg = *reinterpret_cast<const float4*>(g + c);
    float4 bb = *reinterpret_cast<const float4*>(b + c);
    float o0 = dx*rstd*gg.x + bb.x;
    float o1 = dy*rstd*gg.y + bb.y;
    float o2 = dz*rstd*gg.z + bb.z;
    float o3 = dw*rstd*gg.w + bb.w;
    uint2 w2 = make_uint2(pack2(o0, o1), pack2(o2, o3));
    *reinterpret_cast<uint2*>(out + (size_t)row*HW2 + tid*2) = w2;
}

// ============================================================================
// fp16 GEMM: A [M][K2] half2 words (k-pairs), B [K2][N] half2 words.
// 128x128 tile, 32-k (16 words) per stage, 3-stage cp.async, m16n8k16.
// OUT modes: 0 = f32 + residual, 2 = half2+relu,
//            3 = half2 with cols<Hd scaled 0.125 (fused QKV), 4 = f32 plain
// ============================================================================
#define GKTW 16     // k-words per stage (32 k)
#define APAD 20
#define BPAD 136
#define GEMM_SMEM ((3*128*APAD + 3*GKTW*BPAD) * 4)

template<int OM>
__global__ void __launch_bounds__(256, 2)
gemm_hk(const unsigned* __restrict__ A,
        const unsigned* __restrict__ B,
        const float* __restrict__ bias,
        const float* __restrict__ R,
        void* __restrict__ Cv,
        int M, int N, int K2)
{
    extern __shared__ unsigned gsm[];
    unsigned* As = gsm;                 // [3][128][APAD]
    unsigned* Bs = gsm + 3*128*APAD;    // [3][GKTW][BPAD]

    int tid = threadIdx.x;
    int wid = tid >> 5, lane = tid & 31;
    int g = lane >> 2, t = lane & 3;
    int wm = (wid >> 2) * 64;
    int wn = (wid & 3) * 32;
    int rowBase = blockIdx.y * 128;
    int colBase = blockIdx.x * 128;

    float acc[4][4][4];
    #pragma unroll
    for (int mi = 0; mi < 4; mi++)
        #pragma unroll
        for (int ni = 0; ni < 4; ni++)
            #pragma unroll
            for (int r = 0; r < 4; r++) acc[mi][ni][r] = 0.0f;

    int nst = K2 / GKTW;

    auto loadStage = [&](int st, int k0w) {
        unsigned* Adst = As + st*128*APAD;
        unsigned* Bdst = Bs + st*GKTW*BPAD;
        #pragma unroll
        for (int i = 0; i < 2; i++) {
            int li = tid + i * 256;
            int r = li >> 2, kq = (li & 3) * 4;
            cpa16((unsigned)__cvta_generic_to_shared(&Adst[r*APAD + kq]),
                  &A[(size_t)(rowBase + r) * K2 + k0w + kq]);
        }
        #pragma unroll
        for (int i = 0; i < 2; i++) {
            int li = tid + i * 256;
            int r = li >> 5, cq = (li & 31) * 4;
            int gc = colBase + cq;
            cpa16p((unsigned)__cvta_generic_to_shared(&Bdst[r*BPAD + cq]),
                   &B[(size_t)(k0w + r) * N + gc], (gc + 4 <= N) ? 16 : 0);
        }
        cp_commit();
    };

    auto computeStage = [&](int st) {
        const unsigned* Asrc = As + st*128*APAD;
        const unsigned* Bsrc = Bs + st*GKTW*BPAD;
        #pragma unroll
        for (int kk2 = 0; kk2 < GKTW; kk2 += 8) {   // 2 x k16 chunks
            unsigned a[4][4], b[4][2];
            #pragma unroll
            for (int mi = 0; mi < 4; mi++) {
                int m = wm + mi * 16 + g;
                a[mi][0] = Asrc[m*APAD       + kk2 + t];
                a[mi][1] = Asrc[(m + 8)*APAD + kk2 + t];
                a[mi][2] = Asrc[m*APAD       + kk2 + 4 + t];
                a[mi][3] = Asrc[(m + 8)*APAD + kk2 + 4 + t];
            }
            #pragma unroll
            for (int ni = 0; ni < 4; ni++) {
                int n = wn + ni * 8 + g;
                b[ni][0] = Bsrc[(kk2 + t)*BPAD     + n];
                b[ni][1] = Bsrc[(kk2 + 4 + t)*BPAD + n];
            }
            #pragma unroll
            for (int mi = 0; mi < 4; mi++)
                #pragma unroll
                for (int ni = 0; ni < 4; ni++)
                    mma16(acc[mi][ni], a[mi][0], a[mi][1], a[mi][2], a[mi][3],
                          b[ni][0], b[ni][1]);
        }
    };

    loadStage(0, 0);
    if (nst > 1) loadStage(1, GKTW);

    for (int s = 0; s < nst; s++) {
        if (s + 1 < nst) cp_wait<1>(); else cp_wait<0>();
        __syncthreads();
        computeStage(s % 3);
        if (s + 2 < nst) loadStage((s + 2) % 3, (s + 2) * GKTW);
    }

    #pragma unroll
    for (int mi = 0; mi < 4; mi++) {
        #pragma unroll
        for (int ni = 0; ni < 4; ni++) {
            int r0 = rowBase + wm + mi * 16 + g;
            int c0 = colBase + wn + ni * 8 + 2 * t;   // even
            if (c0 < N) {
                float bx = bias[c0], by = bias[c0 + 1];
                float v00 = acc[mi][ni][0] + bx;
                float v01 = acc[mi][ni][1] + by;
                float v10 = acc[mi][ni][2] + bx;
                float v11 = acc[mi][ni][3] + by;
                if (OM == 0) {
                    float* C = (float*)Cv;
                    float2 ra = *(const float2*)&R[(size_t)r0 * N + c0];
                    float2 rb = *(const float2*)&R[(size_t)(r0 + 8) * N + c0];
                    *(float2*)&C[(size_t)r0 * N + c0]       = make_float2(v00 + ra.x, v01 + ra.y);
                    *(float2*)&C[(size_t)(r0 + 8) * N + c0] = make_float2(v10 + rb.x, v11 + rb.y);
                } else if (OM == 4) {
                    float* C = (float*)Cv;
                    *(float2*)&C[(size_t)r0 * N + c0]       = make_float2(v00, v01);
                    *(float2*)&C[(size_t)(r0 + 8) * N + c0] = make_float2(v10, v11);
                } else {
                    if (OM == 2) {
                        v00 = fmaxf(v00, 0.f); v01 = fmaxf(v01, 0.f);
                        v10 = fmaxf(v10, 0.f); v11 = fmaxf(v11, 0.f);
                    }
                    if (OM == 3 && c0 < Hd) {
                        v00 *= 0.125f; v01 *= 0.125f;
                        v10 *= 0.125f; v11 *= 0.125f;
                    }
                    unsigned* C = (unsigned*)Cv;
                    int n2 = N >> 1;
                    C[(size_t)r0 * n2 + (c0 >> 1)]       = pack2(v00, v01);
                    C[(size_t)(r0 + 8) * n2 + (c0 >> 1)] = pack2(v10, v11);
                }
            }
        }
    }
}

// ============================================================================
// fp16 flash attention. Q/K/V half2 words in g_qkv (q pre-scaled by 1/8).
// 3-buffer K/V ring, ONE __syncthreads per k-tile (warps may drift within a
// tile -> softmax MUFU overlaps other warps' tensor work). P in registers.
// PV B-fragments gathered directly from raw V tile via 2x LDS + byte_perm
// (mapping verified identical to the former Vt-transpose path).
// ============================================================================
#define KPAD 36
#define VPAD 36
#define FLASH_SMEM ((3*128*KPAD + 3*128*VPAD) * 4 + 512)

__global__ void __launch_bounds__(256, 1)
flash_attn(const unsigned* __restrict__ qkv,
           const unsigned char* __restrict__ mask,
           unsigned* __restrict__ ctx)
{
    extern __shared__ unsigned fsm[];
    unsigned* Ks = fsm;                         // [3][128][KPAD]
    unsigned* Vs = Ks + 3*128*KPAD;             // [3][128][VPAD]
    unsigned char* Ms = (unsigned char*)(Vs + 3*128*VPAD);   // 3*128

    int bi = blockIdx.y;
    int b = bi >> 3, h = bi & 7;
    int qBase = blockIdx.x * 128;
    const unsigned* Qg = qkv + (size_t)b*Sd*QW2 + h*(DKd/2);
    const unsigned* Kg = qkv + (size_t)b*Sd*QW2 + HW2     + h*(DKd/2);
    const unsigned* Vg = qkv + (size_t)b*Sd*QW2 + 2*HW2   + h*(DKd/2);
    const unsigned char* mr = mask + (size_t)b*Sd;
    unsigned* Cg = ctx + (size_t)b*Sd*HW2 + h*(DKd/2);

    int tid = threadIdx.x;
    int wid = tid >> 5, lane = tid & 31;
    int g = lane >> 2, t = lane & 3;
    int wm = wid * 16;

    // Q fragments: 4 chunks of k16 (DK=64)
    unsigned qf[4][4];
    {
        int r0 = qBase + wm + g, r1 = r0 + 8;
        #pragma unroll
        for (int c = 0; c < 4; c++) {
            qf[c][0] = Qg[(size_t)r0*QW2 + c*8 + t];
            qf[c][1] = Qg[(size_t)r1*QW2 + c*8 + t];
            qf[c][2] = Qg[(size_t)r0*QW2 + c*8 + 4 + t];
            qf[c][3] = Qg[(size_t)r1*QW2 + c*8 + 4 + t];
        }
    }

    float m0 = -1e30f, m1 = -1e30f, l0 = 0.f, l1 = 0.f;
    float o[8][4];
    #pragma unroll
    for (int i = 0; i < 8; i++)
        #pragma unroll
        for (int r = 0; r < 4; r++) o[i][r] = 0.f;

    auto loadTile = [&](int kt, int buf) {
        unsigned* Ktile = Ks + buf*128*KPAD;
        unsigned* Vtile = Vs + buf*128*VPAD;
        #pragma unroll
        for (int i = 0; i < 4; i++) {
            int li = tid + i * 256;
            int r = li >> 3, cq = (li & 7) * 4;
            cpa16((unsigned)__cvta_generic_to_shared(&Ktile[r*KPAD + cq]),
                  &Kg[(size_t)(kt*128 + r)*QW2 + cq]);
            cpa16((unsigned)__cvta_generic_to_shared(&Vtile[r*VPAD + cq]),
                  &Vg[(size_t)(kt*128 + r)*QW2 + cq]);
        }
        if (tid < 32) {
            uchar4 mv = *(const uchar4*)&mr[kt*128 + tid*4];
            *(uchar4*)&Ms[buf*128 + tid*4] = mv;
        }
        cp_commit();
    };

    const int NT = Sd / 128;   // 16
    loadTile(0, 0);

    for (int kt = 0; kt < NT; kt++) {
        int buf = kt % 3;
        // Prefetch target (kt+1)%3 never equals the buffer a one-iteration-
        // behind warp may still read ((kt-1)%3) -> safe before the barrier.
        if (kt + 1 < NT) { loadTile(kt + 1, (kt + 1) % 3); cp_wait<1>(); }
        else             { cp_wait<0>(); }
        __syncthreads();   // tile kt visible to all; bounds warp drift to 1 iter

        const unsigned* Ktile = Ks + buf*128*KPAD;
        const unsigned* Vtile = Vs + buf*128*VPAD;
        const unsigned char* Mt = Ms + buf*128;

        // ---- S = Q K^T : 16 rows x 128 keys per warp ----
        float s[16][4];
        #pragma unroll
        for (int ni = 0; ni < 16; ni++)
            #pragma unroll
            for (int r = 0; r < 4; r++) s[ni][r] = 0.f;

        #pragma unroll
        for (int c = 0; c < 4; c++) {
            #pragma unroll
            for (int ni = 0; ni < 16; ni++) {
                int n = ni*8 + g;
                unsigned b0 = Ktile[n*KPAD + c*8 + t];
                unsigned b1 = Ktile[n*KPAD + c*8 + 4 + t];
                mma16(s[ni], qf[c][0], qf[c][1], qf[c][2], qf[c][3], b0, b1);
            }
        }

        // ---- mask + row max ----
        float mt0 = -1e30f, mt1 = -1e30f;
        #pragma unroll
        for (int ni = 0; ni < 16; ni++) {
            int c = ni*8 + 2*t;
            if (Mt[c])     { s[ni][0] = -1e30f; s[ni][2] = -1e30f; }
            if (Mt[c + 1]) { s[ni][1] = -1e30f; s[ni][3] = -1e30f; }
            mt0 = fmaxf(mt0, fmaxf(s[ni][0], s[ni][1]));
            mt1 = fmaxf(mt1, fmaxf(s[ni][2], s[ni][3]));
        }
        mt0 = fmaxf(mt0, __shfl_xor_sync(0xffffffffu, mt0, 1));
        mt0 = fmaxf(mt0, __shfl_xor_sync(0xffffffffu, mt0, 2));
        mt1 = fmaxf(mt1, __shfl_xor_sync(0xffffffffu, mt1, 1));
        mt1 = fmaxf(mt1, __shfl_xor_sync(0xffffffffu, mt1, 2));

        float mn0 = fmaxf(m0, mt0), mn1 = fmaxf(m1, mt1);
        float c0s = __expf(m0 - mn0), c1s = __expf(m1 - mn1);
        m0 = mn0; m1 = mn1;

        // ---- exp in-place + row sums (P stays in registers) ----
        float rs0 = 0.f, rs1 = 0.f;
        #pragma unroll
        for (int ni = 0; ni < 16; ni++) {
            s[ni][0] = __expf(s[ni][0] - m0);
            s[ni][1] = __expf(s[ni][1] - m0);
            s[ni][2] = __expf(s[ni][2] - m1);
            s[ni][3] = __expf(s[ni][3] - m1);
            rs0 += s[ni][0] + s[ni][1];
            rs1 += s[ni][2] + s[ni][3];
        }
        rs0 += __shfl_xor_sync(0xffffffffu, rs0, 1);
        rs0 += __shfl_xor_sync(0xffffffffu, rs0, 2);
        rs1 += __shfl_xor_sync(0xffffffffu, rs1, 1);
        rs1 += __shfl_xor_sync(0xffffffffu, rs1, 2);
        l0 = l0 * c0s + rs0;
        l1 = l1 * c1s + rs1;

        #pragma unroll
        for (int oni = 0; oni < 8; oni++) {
            o[oni][0] *= c0s; o[oni][1] *= c0s;
            o[oni][2] *= c1s; o[oni][3] *= c1s;
        }

        // ---- O += P V : A-frags packed from S regs; B gathered from raw Vs ----
        // b0 for dim d, key-pair kw = kk*8+t: half2(V[2kw][d], V[2kw+1][d])
        //   = byte_perm(Vs[2kw][d>>1], Vs[2kw+1][d>>1], d&1 ? 0x7632 : 0x5410)
        {
            unsigned sel = (g & 1) ? 0x7632u : 0x5410u;
            #pragma unroll
            for (int kk = 0; kk < 8; kk++) {
                unsigned a0 = pack2(s[2*kk][0],   s[2*kk][1]);
                unsigned a1 = pack2(s[2*kk][2],   s[2*kk][3]);
                unsigned a2 = pack2(s[2*kk+1][0], s[2*kk+1][1]);
                unsigned a3 = pack2(s[2*kk+1][2], s[2*kk+1][3]);
                const unsigned* V0a = Vtile + (2*(kk*8 + t))*VPAD;
                const unsigned* V0b = V0a + VPAD;
                const unsigned* V1a = Vtile + (2*(kk*8 + 4 + t))*VPAD;
                const unsigned* V1b = V1a + VPAD;
                #pragma unroll
                for (int oni = 0; oni < 8; oni++) {
                    int dw = oni*4 + (g >> 1);
                    unsigned b0 = __byte_perm(V0a[dw], V0b[dw], sel);
                    unsigned b1 = __byte_perm(V1a[dw], V1b[dw], sel);
                    mma16(o[oni], a0, a1, a2, a3, b0, b1);
                }
            }
        }
        // no trailing barrier: next iteration's single barrier bounds drift
    }

    // ---- epilogue: divide by l, pack half2, write ctx ----
    float i0 = 1.f / l0, i1 = 1.f / l1;
    int r0 = qBase + wm + g, r1 = r0 + 8;
    #pragma unroll
    for (int oni = 0; oni < 8; oni++) {
        int wrd = oni*4 + t;
        Cg[(size_t)r0*HW2 + wrd] = pack2(o[oni][0] * i0, o[oni][1] * i0);
        Cg[(size_t)r1*HW2 + wrd] = pack2(o[oni][2] * i1, o[oni][3] * i1);
    }
}

// ---------------- launch ----------------
extern "C" void kernel_launch(void* const* d_in, const int* in_sizes, int n_in,
                              void* d_out, int out_size)
{
    const int*           src  = (const int*)d_in[0];
    const unsigned char* mask = (const unsigned char*)d_in[1];
    const float* emb  = (const float*)d_in[2];
    const float* Wq   = (const float*)d_in[3];
    const float* bq   = (const float*)d_in[4];
    const float* Wk   = (const float*)d_in[5];
    const float* bk   = (const float*)d_in[6];
    const float* Wv   = (const float*)d_in[7];
    const float* bv   = (const float*)d_in[8];
    const float* Wo   = (const float*)d_in[9];
    const float* bo   = (const float*)d_in[10];
    const float* ln1g = (const float*)d_in[11];
    const float* ln1b = (const float*)d_in[12];
    const float* W1   = (const float*)d_in[13];
    const float* b1   = (const float*)d_in[14];
    const float* W2   = (const float*)d_in[15];
    const float* b2   = (const float*)d_in[16];
    const float* ln2g = (const float*)d_in[17];
    const float* ln2b = (const float*)d_in[18];
    const float* lnfg = (const float*)d_in[19];
    const float* lnfb = (const float*)d_in[20];
    const float* Wg   = (const float*)d_in[21];
    const float* bg   = (const float*)d_in[22];
    float* out = (float*)d_out;

    float *x;   unsigned *h, *qkv, *ctx, *ff;
    unsigned *wqkv, *wo, *w1, *w2, *wg;  float *bqkv;
    cudaGetSymbolAddress((void**)&x,    g_x);
    cudaGetSymbolAddress((void**)&h,    g_h);
    cudaGetSymbolAddress((void**)&qkv,  g_qkv);
    cudaGetSymbolAddress((void**)&ctx,  g_ctx);
    cudaGetSymbolAddress((void**)&ff,   g_ff);
    cudaGetSymbolAddress((void**)&wqkv, g_wqkv);
    cudaGetSymbolAddress((void**)&wo,   g_wo);
    cudaGetSymbolAddress((void**)&w1,   g_w1);
    cudaGetSymbolAddress((void**)&w2,   g_w2);
    cudaGetSymbolAddress((void**)&wg,   g_wg);
    cudaGetSymbolAddress((void**)&bqkv, g_bqkv);

    static bool attr_set = false;
    if (!attr_set) {
        cudaFuncSetAttribute(flash_attn,
                             cudaFuncAttributeMaxDynamicSharedMemorySize, FLASH_SMEM);
        cudaFuncSetAttribute(gemm_hk<0>,
                             cudaFuncAttributeMaxDynamicSharedMemorySize, GEMM_SMEM);
        cudaFuncSetAttribute(gemm_hk<2>,
                             cudaFuncAttributeMaxDynamicSharedMemorySize, GEMM_SMEM);
        cudaFuncSetAttribute(gemm_hk<3>,
                             cudaFuncAttributeMaxDynamicSharedMemorySize, GEMM_SMEM);
        cudaFuncSetAttribute(gemm_hk<4>,
                             cudaFuncAttributeMaxDynamicSharedMemorySize, GEMM_SMEM);
        attr_set = true;
    }

    // ---- prepack weights to half2 words ----
    pack_qkv_kernel<<<1184, 256>>>(Wq, Wk, Wv, wqkv);
    pack_bqkv_kernel<<<(Lx*QKVW + 255)/256, 256>>>(bq, bk, bv, bqkv);
    conv_pack<<<1184, 256>>>(Wo, wo, Hd,    Lx*HW2*Hd);
    conv_pack<<<1184, 256>>>(W1, w1, FFd,   Lx*HW2*FFd);
    conv_pack<<<1184, 256>>>(W2, w2, Hd,    Lx*FW2*Hd);
    conv_pack<<<1184, 256>>>(Wg, wg, Vocab, HW2*Vocab);

    embed_kernel<<<(Nt*Hd + 255)/256, 256>>>(src, emb, x);

    dim3 gQKV(QKVW/128, Nt/128);
    dim3 gH(Hd/128,  Nt/128);
    dim3 gF(FFd/128, Nt/128);
    dim3 gV((Vocab+127)/128, Nt/128);

    for (int l = 0; l < Lx; l++) {
        layernorm_kernel<<<Nt, 128>>>(x, ln1g + (size_t)l*Hd, ln1b + (size_t)l*Hd, h);

        // fused QKV (q cols pre-scaled by 1/8, half2 out)
        gemm_hk<3><<<gQKV, 256, GEMM_SMEM>>>(h, wqkv + (size_t)l*HW2*QKVW, bqkv + (size_t)l*QKVW,
                                             nullptr, qkv, Nt, QKVW, HW2);

        flash_attn<<<dim3(Sd/128, Bd*NHd), 256, FLASH_SMEM>>>(qkv, mask, ctx);

        // x = x + ctx @ Wo + bo
        gemm_hk<0><<<gH, 256, GEMM_SMEM>>>(ctx, wo + (size_t)l*HW2*Hd, bo + (size_t)l*Hd,
                                           x, x, Nt, Hd, HW2);

        layernorm_kernel<<<Nt, 128>>>(x, ln2g + (size_t)l*Hd, ln2b + (size_t)l*Hd, h);

        // ff = relu(h @ W1 + b1) (half2 out)
        gemm_hk<2><<<gF, 256, GEMM_SMEM>>>(h, w1 + (size_t)l*HW2*FFd, b1 + (size_t)l*FFd,
                                           nullptr, ff, Nt, FFd, HW2);
        // x = x + ff @ W2 + b2
        gemm_hk<0><<<gH, 256, GEMM_SMEM>>>(ff, w2 + (size_t)l*FW2*Hd, b2 + (size_t)l*Hd,
                                           x, x, Nt, Hd, FW2);
    }

    layernorm_kernel<<<Nt, 128>>>(x, lnfg, lnfb, h);
    gemm_hk<4><<<gV, 256, GEMM_SMEM>>>(h, wg, bg, nullptr, out, Nt, Vocab, HW2);
}